// round 1
// baseline (speedup 1.0000x reference)
#include <cuda_runtime.h>
#include <cuda_bf16.h>
#include <math.h>

#define BB 4
#define LL 2048
#define EMBD 256
#define NHD 8
#define HPD 64
#define DST 256
#define DIN 512
#define CVD 1024
#define DPJ 1544
#define CHKL 64
#define NCH 32
#define ROWS (BB*LL)

// ---------------- scratch (static device globals; no allocation) ----------------
__device__ float g_h[ROWS*EMBD];
__device__ float g_u[ROWS*EMBD];
__device__ float g_zx[(size_t)ROWS*DPJ];
__device__ float g_xBC[(size_t)ROWS*CVD];
__device__ float g_dt[ROWS*NHD];
__device__ float g_dA[ROWS*NHD];
__device__ float g_Acs[BB*NCH*NHD*CHKL];
__device__ float g_T[BB*NCH*NHD];
__device__ float g_CB[BB*NCH*CHKL*CHKL];
__device__ float g_state[(size_t)BB*NCH*NHD*HPD*DST]; // [b][c][h][p][n]
__device__ float g_y[(size_t)ROWS*DIN];
__device__ float g_yn[(size_t)ROWS*DIN];

// ---------------- helpers ----------------
__device__ __forceinline__ float blkReduce(float v, float* sh){
  int lane = threadIdx.x & 31, w = threadIdx.x >> 5;
  #pragma unroll
  for(int o=16;o;o>>=1) v += __shfl_xor_sync(0xffffffffu, v, o);
  if(lane==0) sh[w]=v;
  __syncthreads();
  float r = (threadIdx.x < 8) ? sh[threadIdx.x] : 0.f;
  if(w==0){
    #pragma unroll
    for(int o=4;o;o>>=1) r += __shfl_xor_sync(0xffffffffu, r, o);
    if(lane==0) sh[0]=r;
  }
  __syncthreads();
  return sh[0];
}

// ---------------- kernels ----------------
__global__ void k_embed(const float* __restrict__ x, const float* __restrict__ emb){
  int row = blockIdx.x;
  float xv = x[row];
  int idx = (int)(255.0f * xv);
  idx = min(max(idx,0),255);
  g_h[(size_t)row*EMBD + threadIdx.x] = emb[(size_t)idx*EMBD + threadIdx.x];
}

__global__ void k_rmsnorm(const float* __restrict__ in, const float* __restrict__ w,
                          float* __restrict__ out, int dim){
  __shared__ float sh[32];
  int row = blockIdx.x;
  const float* r = in + (size_t)row*dim;
  float s = 0.f;
  for(int i=threadIdx.x;i<dim;i+=blockDim.x){ float v=r[i]; s += v*v; }
  s = blkReduce(s, sh);
  float sc = rsqrtf(s/(float)dim + 1e-5f);
  for(int i=threadIdx.x;i<dim;i+=blockDim.x) out[(size_t)row*dim+i] = r[i]*sc*w[i];
}

// C[M,N] = A[M,K] @ B[K,N] (+Res). BM=128, BN=64, BK=16, 256 threads, 8x4 microtile.
__global__ void __launch_bounds__(256) k_sgemm(
    const float* __restrict__ A, const float* __restrict__ B,
    float* __restrict__ C, const float* __restrict__ Res,
    int M, int N, int K){
  __shared__ float As[16][132];
  __shared__ float Bs[16][68];
  int bm = blockIdx.y*128, bn = blockIdx.x*64;
  int tid = threadIdx.x;
  int tr = tid >> 4, tc = tid & 15;
  float acc[8][4];
  #pragma unroll
  for(int i=0;i<8;i++)
    #pragma unroll
    for(int j=0;j<4;j++) acc[i][j]=0.f;

  for(int k0=0;k0<K;k0+=16){
    #pragma unroll
    for(int i=0;i<8;i++){
      int idx = tid + i*256;
      int m = idx >> 4, k = idx & 15;
      As[k][m] = A[(size_t)(bm+m)*K + k0 + k];
    }
    #pragma unroll
    for(int i=0;i<4;i++){
      int idx = tid + i*256;
      int n = idx & 63, k = idx >> 6;
      int col = bn + n;
      Bs[k][n] = (col < N) ? B[(size_t)(k0+k)*N + col] : 0.f;
    }
    __syncthreads();
    #pragma unroll
    for(int k=0;k<16;k++){
      float a[8], b[4];
      #pragma unroll
      for(int i=0;i<8;i++) a[i] = As[k][tr*8+i];
      #pragma unroll
      for(int j=0;j<4;j++) b[j] = Bs[k][tc*4+j];
      #pragma unroll
      for(int i=0;i<8;i++)
        #pragma unroll
        for(int j=0;j<4;j++) acc[i][j] += a[i]*b[j];
    }
    __syncthreads();
  }
  #pragma unroll
  for(int i=0;i<8;i++){
    int m = bm + tr*8 + i;
    #pragma unroll
    for(int j=0;j<4;j++){
      int n = bn + tc*4 + j;
      if(n < N){
        float v = acc[i][j];
        if(Res) v += Res[(size_t)m*N + n];
        C[(size_t)m*N + n] = v;
      }
    }
  }
}

// depthwise causal conv(width4) + SiLU; plus dt = softplus(raw+bias), dA = -exp(A_log)*dt
__global__ void k_conv(const float* __restrict__ cw, const float* __restrict__ cb,
                       const float* __restrict__ dtb, const float* __restrict__ alog){
  int row = blockIdx.x; int b = row/LL, t = row%LL;
  int tid = threadIdx.x;
  #pragma unroll
  for(int j=0;j<4;j++){
    int ch = tid + j*256;
    float acc = cb[ch];
    #pragma unroll
    for(int k=0;k<4;k++){
      int tt = t-3+k;
      if(tt>=0) acc += g_zx[(size_t)(b*LL+tt)*DPJ + DIN + ch]*cw[ch*4+k];
    }
    g_xBC[(size_t)row*CVD + ch] = acc/(1.f+expf(-acc));
  }
  if(tid < NHD){
    float v = g_zx[(size_t)row*DPJ + DIN + CVD + tid] + dtb[tid];
    float dtv = fmaxf(v,0.f) + log1pf(expf(-fabsf(v)));
    g_dt[row*NHD+tid] = dtv;
    g_dA[row*NHD+tid] = -expf(alog[tid])*dtv;
  }
}

__global__ void k_cumsum(){
  int bc = blockIdx.x; int h = threadIdx.x;
  if(h >= NHD) return;
  int b = bc/NCH, c = bc%NCH;
  float s = 0.f;
  for(int l=0;l<CHKL;l++){
    s += g_dA[(size_t)(b*LL + c*CHKL + l)*NHD + h];
    g_Acs[(bc*NHD+h)*CHKL + l] = s;
  }
  g_T[bc*NHD+h] = s;
}

// CB[l,s] = sum_n Cm[l,n]*Bm[s,n], per (b,c)
__global__ void __launch_bounds__(256) k_cb(){
  int bc = blockIdx.x; int b = bc/NCH, c = bc%NCH;
  __shared__ float Cs[CHKL][65];
  __shared__ float Bs[CHKL][65];
  size_t rowb = (size_t)(b*LL + c*CHKL);
  int tid = threadIdx.x, tr = tid>>4, tc = tid&15;
  float acc[4][4];
  #pragma unroll
  for(int i=0;i<4;i++)
    #pragma unroll
    for(int j=0;j<4;j++) acc[i][j]=0.f;
  for(int n0=0;n0<DST;n0+=64){
    #pragma unroll
    for(int i=0;i<16;i++){
      int idx = tid + i*256; int l = idx>>6, k = idx&63;
      Cs[l][k] = g_xBC[(rowb+l)*CVD + DIN+DST + n0 + k];
      Bs[l][k] = g_xBC[(rowb+l)*CVD + DIN + n0 + k];
    }
    __syncthreads();
    #pragma unroll 8
    for(int k=0;k<64;k++){
      float a[4], bb[4];
      #pragma unroll
      for(int i=0;i<4;i++) a[i] = Cs[tr*4+i][k];
      #pragma unroll
      for(int j=0;j<4;j++) bb[j] = Bs[tc*4+j][k];
      #pragma unroll
      for(int i=0;i<4;i++)
        #pragma unroll
        for(int j=0;j<4;j++) acc[i][j] += a[i]*bb[j];
    }
    __syncthreads();
  }
  size_t ob = (size_t)bc*CHKL*CHKL;
  #pragma unroll
  for(int i=0;i<4;i++)
    #pragma unroll
    for(int j=0;j<4;j++)
      g_CB[ob + (tr*4+i)*64 + tc*4+j] = acc[i][j];
}

// state[b,c,h,p,n] = sum_l Bm[l,n]*exp(T-Acs[l])*dt[l]*xh[l,h,p]
__global__ void __launch_bounds__(256) k_chunkstate(){
  int bc = blockIdx.x, h = blockIdx.y;
  int b = bc/NCH, c = bc%NCH;
  __shared__ float xsh[CHKL][HPD];
  __shared__ float coef[CHKL];
  size_t rowb = (size_t)(b*LL + c*CHKL);
  int tid = threadIdx.x;
  #pragma unroll
  for(int i=0;i<16;i++){
    int idx = tid + i*256; int l = idx>>6, p = idx&63;
    xsh[l][p] = g_xBC[(rowb+l)*CVD + h*HPD + p];
  }
  if(tid < CHKL){
    float T = g_T[bc*NHD+h];
    coef[tid] = expf(T - g_Acs[(bc*NHD+h)*CHKL + tid]) * g_dt[(rowb+tid)*NHD + h];
  }
  __syncthreads();
  int n = tid;
  float acc[HPD];
  #pragma unroll
  for(int p=0;p<HPD;p++) acc[p]=0.f;
  for(int l=0;l<CHKL;l++){
    float bv = g_xBC[(rowb+l)*CVD + DIN + n] * coef[l];
    #pragma unroll
    for(int p=0;p<HPD;p++) acc[p] += bv * xsh[l][p];
  }
  size_t base = ((size_t)bc*NHD + h)*(size_t)HPD*DST;
  #pragma unroll
  for(int p=0;p<HPD;p++) g_state[base + (size_t)p*DST + n] = acc[p];
}

// inter-chunk scan: replace per-chunk states with prefix (exclusive) states
__global__ void k_scan(){
  int bh = blockIdx.y; int b = bh>>3, h = bh&7;
  int idx = blockIdx.x*256 + threadIdx.x; // 0..16383 over (p,n)
  float run = 0.f;
  for(int c=0;c<NCH;c++){
    size_t off = (((size_t)(b*NCH+c)*NHD + h)*(size_t)HPD*DST) + idx;
    float s = g_state[off];
    g_state[off] = run;
    run = run*expf(g_T[(b*NCH+c)*NHD + h]) + s;
  }
}

// Y[l,h,p] = sum_{s<=l} CB[l,s]exp(Acs[l]-Acs[s])dt[s]*xh[s,p]
//          + exp(Acs[l]) * sum_n Cm[l,n]*state_prev[p,n] + D[h]*xh[l,p]
__global__ void __launch_bounds__(256) k_y(const float* __restrict__ Dp){
  extern __shared__ float sm[];
  float* xsh = sm;                    // 64*64   = 4096
  float* cbl = sm + 4096;             // 64*65   = 4160
  float* st  = sm + 4096 + 4160;      // 256*68  = 17408
  float* cme = sm + 4096 + 4160 + 17408; // 64*257 = 16448
  __shared__ float acs_s[64], dtl_s[64];
  int bc = blockIdx.x, h = blockIdx.y;
  int b = bc/NCH, c = bc%NCH;
  size_t rowb = (size_t)(b*LL + c*CHKL);
  int tid = threadIdx.x;
  if(tid < 64){
    acs_s[tid] = g_Acs[(bc*NHD+h)*CHKL + tid];
    dtl_s[tid] = g_dt[(rowb+tid)*NHD + h];
  }
  __syncthreads();
  #pragma unroll
  for(int i=0;i<16;i++){
    int idx = tid + i*256; int l = idx>>6, p = idx&63;
    xsh[idx] = g_xBC[(rowb+l)*CVD + h*HPD + p];
  }
  #pragma unroll
  for(int i=0;i<16;i++){
    int idx = tid + i*256; int l = idx>>6, s = idx&63;
    cbl[l*65+s] = (s<=l) ? g_CB[(size_t)bc*4096 + idx]*expf(acs_s[l]-acs_s[s])*dtl_s[s] : 0.f;
  }
  size_t stb = ((size_t)bc*NHD + h)*(size_t)HPD*DST;
  #pragma unroll
  for(int i=0;i<64;i++){
    int idx = tid + i*256; int p = idx>>8, n = idx&255;
    st[n*68+p] = g_state[stb + idx];
  }
  #pragma unroll
  for(int i=0;i<64;i++){
    int idx = tid + i*256; int l = idx>>8, n = idx&255;
    cme[l*257+n] = g_xBC[(rowb+l)*CVD + DIN+DST + n]*expf(acs_s[l]);
  }
  __syncthreads();

  int l = tid>>2, p0 = (tid&3)<<4;
  float acc[16];
  #pragma unroll
  for(int i=0;i<16;i++) acc[i]=0.f;
  // intra-chunk (causal) part
  for(int s=0;s<=l;s++){
    float cv = cbl[l*65+s];
    const float4* xr = (const float4*)&xsh[s*64+p0];
    #pragma unroll
    for(int q=0;q<4;q++){
      float4 xv = xr[q];
      acc[q*4+0] += cv*xv.x; acc[q*4+1] += cv*xv.y;
      acc[q*4+2] += cv*xv.z; acc[q*4+3] += cv*xv.w;
    }
  }
  // inter-chunk part
  #pragma unroll 4
  for(int n=0;n<DST;n++){
    float cv = cme[l*257+n];
    const float4* sr = (const float4*)&st[n*68+p0];
    #pragma unroll
    for(int q=0;q<4;q++){
      float4 sv = sr[q];
      acc[q*4+0] += cv*sv.x; acc[q*4+1] += cv*sv.y;
      acc[q*4+2] += cv*sv.z; acc[q*4+3] += cv*sv.w;
    }
  }
  float Dh = Dp[h];
  const float* xo = &xsh[l*64+p0];
  float* yo = &g_y[(rowb+l)*DIN + h*HPD + p0];
  #pragma unroll
  for(int i=0;i<16;i++) yo[i] = acc[i] + Dh*xo[i];
}

__global__ void k_gatednorm(const float* __restrict__ gw){
  __shared__ float sh[32];
  int row = blockIdx.x;
  int i0 = threadIdx.x, i1 = threadIdx.x + 256;
  float z0 = g_zx[(size_t)row*DPJ + i0], y0 = g_y[(size_t)row*DIN + i0];
  float z1 = g_zx[(size_t)row*DPJ + i1], y1 = g_y[(size_t)row*DIN + i1];
  float v0 = y0 * (z0/(1.f+expf(-z0)));
  float v1 = y1 * (z1/(1.f+expf(-z1)));
  float s = v0*v0 + v1*v1;
  s = blkReduce(s, sh);
  float sc = rsqrtf(s/(float)DIN + 1e-5f);
  g_yn[(size_t)row*DIN + i0] = v0*sc*gw[i0];
  g_yn[(size_t)row*DIN + i1] = v1*sc*gw[i1];
}

// ---------------- launch ----------------
extern "C" void kernel_launch(void* const* d_in, const int* in_sizes, int n_in,
                              void* d_out, int out_size){
  const float* x    = (const float*)d_in[0];
  const float* emb  = (const float*)d_in[1];
  const float* inw  = (const float*)d_in[2];
  const float* cw   = (const float*)d_in[3];
  const float* cb   = (const float*)d_in[4];
  const float* dtb  = (const float*)d_in[5];
  const float* alog = (const float*)d_in[6];
  const float* Dp   = (const float*)d_in[7];
  const float* gw   = (const float*)d_in[8];
  const float* ow   = (const float*)d_in[9];
  const float* nw   = (const float*)d_in[10];
  const float* nfw  = (const float*)d_in[11];
  const float* hw   = (const float*)d_in[12];
  float* out = (float*)d_out;

  float *ph, *pu, *pzx, *pyn;
  cudaGetSymbolAddress((void**)&ph,  g_h);
  cudaGetSymbolAddress((void**)&pu,  g_u);
  cudaGetSymbolAddress((void**)&pzx, g_zx);
  cudaGetSymbolAddress((void**)&pyn, g_yn);
  cudaFuncSetAttribute(k_y, cudaFuncAttributeMaxDynamicSharedMemorySize, 168448);

  k_embed<<<ROWS,256>>>(x, emb);
  for(int i=0;i<2;i++){
    k_rmsnorm<<<ROWS,256>>>(ph, nw + i*EMBD, pu, EMBD);
    k_sgemm<<<dim3(25,64),256>>>(pu, inw + (size_t)i*EMBD*DPJ, pzx, nullptr, ROWS, DPJ, EMBD);
    k_conv<<<ROWS,256>>>(cw + i*CVD*4, cb + i*CVD, dtb + i*NHD, alog + i*NHD);
    k_cumsum<<<BB*NCH,32>>>();
    k_cb<<<BB*NCH,256>>>();
    k_chunkstate<<<dim3(BB*NCH,NHD),256>>>();
    k_scan<<<dim3(64,BB*NHD),256>>>();
    k_y<<<dim3(BB*NCH,NHD),256,168448>>>(Dp + i*NHD);
    k_gatednorm<<<ROWS,256>>>(gw + i*DIN);
    k_sgemm<<<dim3(4,64),256>>>(pyn, ow + (size_t)i*DIN*EMBD, ph, ph, ROWS, EMBD, DIN);
  }
  k_rmsnorm<<<ROWS,256>>>(ph, nfw, pu, EMBD);
  k_sgemm<<<dim3(4,64),256>>>(pu, hw, out, nullptr, ROWS, EMBD, EMBD);
}

// round 4
// speedup vs baseline: 1.2450x; 1.2450x over previous
#include <cuda_runtime.h>
#include <cuda_bf16.h>
#include <math.h>
#include <stdint.h>

#define BB 4
#define LL 2048
#define EMBD 256
#define NHD 8
#define HPD 64
#define DST 256
#define DIN 512
#define CVD 1024
#define DPJ 1544
#define CHKL 64
#define NCH 32
#define ROWS (BB*LL)
#define NPAD_IN 1664

// ---------------- scratch (static device globals; no allocation) ----------------
__device__ float g_h[ROWS*EMBD];
__device__ float g_zx[(size_t)ROWS*DPJ];
__device__ float g_xBC[(size_t)ROWS*CVD];
__device__ float g_dt[ROWS*NHD];
__device__ float g_dA[ROWS*NHD];
__device__ float g_Acs[BB*NCH*NHD*CHKL];
__device__ float g_T[BB*NCH*NHD];
__device__ float g_CB[BB*NCH*CHKL*CHKL];
__device__ float g_state[(size_t)BB*NCH*NHD*HPD*DST]; // [b][c][h][p][n]
__device__ float g_y[(size_t)ROWS*DIN];
__device__ __nv_bfloat16 g_Ab[(size_t)ROWS*1536];     // activations, split-bf16, K3-major
__device__ __nv_bfloat16 g_Wb[(size_t)NPAD_IN*1536];  // weights, [n][K3] K-major

// ---------------- helpers ----------------
__device__ __forceinline__ uint32_t smem_u32(const void* p){
  uint32_t a;
  asm("{ .reg .u64 t; cvta.to.shared.u64 t, %1; cvt.u32.u64 %0, t; }" : "=r"(a) : "l"(p));
  return a;
}

__device__ __forceinline__ float blkReduce(float v, float* sh){
  int lane = threadIdx.x & 31, w = threadIdx.x >> 5;
  #pragma unroll
  for(int o=16;o;o>>=1) v += __shfl_xor_sync(0xffffffffu, v, o);
  if(lane==0) sh[w]=v;
  __syncthreads();
  float r = (threadIdx.x < 8) ? sh[threadIdx.x] : 0.f;
  if(w==0){
    #pragma unroll
    for(int o=4;o;o>>=1) r += __shfl_xor_sync(0xffffffffu, r, o);
    if(lane==0) sh[0]=r;
  }
  __syncthreads();
  return sh[0];
}

#define CPA16(sm, gp) \
  asm volatile("cp.async.cg.shared.global [%0], [%1], 16;" :: "r"(sm), "l"(gp))
#define CPA_COMMIT() asm volatile("cp.async.commit_group;" ::: "memory")
#define CPA_WAIT0()  asm volatile("cp.async.wait_group 0;" ::: "memory")

#define LDSM4(r0,r1,r2,r3,addr) \
  asm volatile("ldmatrix.sync.aligned.m8n8.x4.shared.b16 {%0,%1,%2,%3}, [%4];" \
    : "=r"(r0),"=r"(r1),"=r"(r2),"=r"(r3) : "r"(addr))

#define MMA16816(d, a, b0, b1) \
  asm volatile("mma.sync.aligned.m16n8k16.row.col.f32.bf16.bf16.f32 " \
    "{%0,%1,%2,%3}, {%4,%5,%6,%7}, {%8,%9}, {%0,%1,%2,%3};" \
    : "+f"((d)[0]),"+f"((d)[1]),"+f"((d)[2]),"+f"((d)[3]) \
    : "r"((a)[0]),"r"((a)[1]),"r"((a)[2]),"r"((a)[3]), "r"(b0),"r"(b1))

// ---------------- elementwise kernels ----------------
__global__ void k_embed(const float* __restrict__ x, const float* __restrict__ emb){
  int row = blockIdx.x;
  float xv = x[row];
  int idx = (int)(255.0f * xv);
  idx = min(max(idx,0),255);
  g_h[(size_t)row*EMBD + threadIdx.x] = emb[(size_t)idx*EMBD + threadIdx.x];
}

// rmsnorm(256) -> split-bf16 activations [row][768] = [hi | hi | lo]
__global__ void k_rmsnorm_b(const float* __restrict__ in, const float* __restrict__ w){
  __shared__ float sh[32];
  int row = blockIdx.x;
  float v = in[(size_t)row*EMBD + threadIdx.x];
  float s = blkReduce(v*v, sh);
  float sc = rsqrtf(s/(float)EMBD + 1e-5f);
  float o = v*sc*w[threadIdx.x];
  __nv_bfloat16 h = __float2bfloat16(o);
  __nv_bfloat16 l = __float2bfloat16(o - __bfloat162float(h));
  size_t b = (size_t)row*768 + threadIdx.x;
  g_Ab[b] = h; g_Ab[b+256] = h; g_Ab[b+512] = l;
}

// gated rmsnorm(512) -> split-bf16 activations [row][1536] = [hi | hi | lo]
__global__ void k_gatednorm_b(const float* __restrict__ gw){
  __shared__ float sh[32];
  int row = blockIdx.x;
  int i0 = threadIdx.x, i1 = threadIdx.x + 256;
  float z0 = g_zx[(size_t)row*DPJ + i0], y0 = g_y[(size_t)row*DIN + i0];
  float z1 = g_zx[(size_t)row*DPJ + i1], y1 = g_y[(size_t)row*DIN + i1];
  float v0 = y0 * (z0/(1.f+expf(-z0)));
  float v1 = y1 * (z1/(1.f+expf(-z1)));
  float s = blkReduce(v0*v0 + v1*v1, sh);
  float sc = rsqrtf(s/(float)DIN + 1e-5f);
  float o0 = v0*sc*gw[i0];
  float o1 = v1*sc*gw[i1];
  size_t b = (size_t)row*1536;
  __nv_bfloat16 h0 = __float2bfloat16(o0);
  __nv_bfloat16 l0 = __float2bfloat16(o0 - __bfloat162float(h0));
  __nv_bfloat16 h1 = __float2bfloat16(o1);
  __nv_bfloat16 l1 = __float2bfloat16(o1 - __bfloat162float(h1));
  g_Ab[b+i0] = h0; g_Ab[b+512+i0] = h0; g_Ab[b+1024+i0] = l0;
  g_Ab[b+i1] = h1; g_Ab[b+512+i1] = h1; g_Ab[b+1024+i1] = l1;
}

// weight prep: W[K][N] fp32 -> Wb[n][3K] = [hi(k) | lo(k) | hi(k)], zero-padded rows n>=N
__global__ void k_prep_w(const float* __restrict__ W, int K, int N, int Npad){
  int K3 = K*3;
  int j = blockIdx.x*256 + threadIdx.x;
  if(j >= Npad*K3) return;
  int n = j / K3, r = j - n*K3;
  int seg = r / K, k = r - seg*K;
  __nv_bfloat16 v = __float2bfloat16(0.f);
  if(n < N){
    float w = W[(size_t)k*N + n];
    __nv_bfloat16 h = __float2bfloat16(w);
    if(seg==1) h = __float2bfloat16(w - __bfloat162float(h));
    v = h;
  }
  g_Wb[(size_t)n*K3 + r] = v;
}

// ---------------- warp-MMA bf16 GEMM ----------------
// C[M,N] = A[M,K3] @ Wb[N,K3]^T (+ Res). 128x128x64 tile, double-buffered cp.async.
__global__ void __launch_bounds__(256,2) k_mgemm(
    const __nv_bfloat16* __restrict__ A, const __nv_bfloat16* __restrict__ Bw,
    float* __restrict__ C, const float* __restrict__ Res, int K3, int ldc, int Nreal)
{
  extern __shared__ __align__(1024) uint8_t smem[];
  const int tid = threadIdx.x;
  const int lane = tid & 31, wid = tid >> 5;
  const int wm = wid >> 2, wn = wid & 3;          // 2 x 4 warps
  const int bm = blockIdx.y << 7, bn = blockIdx.x << 7;

  const uint32_t sbase = smem_u32(smem);          // A0 | A1 | B0 | B1, 16KB each

  // global->smem load mapping (4 x 16B vectors per tile per thread)
  uint32_t sw_off[4];
  const __nv_bfloat16 *ga[4], *gb[4];
  #pragma unroll
  for(int i=0;i<4;i++){
    int idx = tid + i*256, row = idx>>3, seg = idx&7;
    uint32_t off = (uint32_t)(row*128 + seg*16);
    sw_off[i] = off ^ ((off>>3)&0x70u);
    ga[i] = A  + (size_t)(bm+row)*K3 + seg*8;
    gb[i] = Bw + (size_t)(bn+row)*K3 + seg*8;
  }

  // ldmatrix per-lane row bases (A: 4 m16 tiles; B: 2 n16 tiles)
  uint32_t arow[4], axb[4], brow[2], bxb[2];
  const uint32_t half16 = (uint32_t)(lane>>4)*16u;
  #pragma unroll
  for(int mi=0;mi<4;mi++){
    uint32_t r = (uint32_t)(wm*64 + mi*16 + (lane&15));
    arow[mi] = r*128u; axb[mi] = (arow[mi]>>3)&0x70u;
  }
  #pragma unroll
  for(int ni=0;ni<2;ni++){
    uint32_t r = (uint32_t)(wn*32 + ni*16 + (lane&15));
    brow[ni] = r*128u; bxb[ni] = (brow[ni]>>3)&0x70u;
  }

  float acc[4][4][4];
  #pragma unroll
  for(int i=0;i<4;i++)
    #pragma unroll
    for(int j=0;j<4;j++)
      #pragma unroll
      for(int q=0;q<4;q++) acc[i][j][q]=0.f;

  const int NC = K3 >> 6;

  // prologue: stage 0
  {
    #pragma unroll
    for(int i=0;i<4;i++){
      CPA16(sbase + sw_off[i],         ga[i]);
      CPA16(sbase + 32768 + sw_off[i], gb[i]);
    }
    CPA_COMMIT();
  }

  for(int c=0;c<NC;c++){
    CPA_WAIT0();
    __syncthreads();
    if(c+1 < NC){
      uint32_t st = (uint32_t)((c+1)&1)*16384u;
      int k0 = (c+1)<<6;
      #pragma unroll
      for(int i=0;i<4;i++){
        CPA16(sbase + st + sw_off[i],         ga[i] + k0);
        CPA16(sbase + 32768 + st + sw_off[i], gb[i] + k0);
      }
      CPA_COMMIT();
    }
    const uint32_t sa = sbase + (uint32_t)(c&1)*16384u;
    const uint32_t sb = sa + 32768u;
    #pragma unroll
    for(int s=0;s<4;s++){
      const uint32_t col = (uint32_t)(s*32) + half16;
      uint32_t a[4][4], b[2][4];
      #pragma unroll
      for(int mi=0;mi<4;mi++)
        LDSM4(a[mi][0],a[mi][1],a[mi][2],a[mi][3], sa + arow[mi] + (col ^ axb[mi]));
      #pragma unroll
      for(int ni=0;ni<2;ni++)
        LDSM4(b[ni][0],b[ni][1],b[ni][2],b[ni][3], sb + brow[ni] + (col ^ bxb[ni]));
      #pragma unroll
      for(int mi=0;mi<4;mi++){
        #pragma unroll
        for(int nj=0;nj<4;nj++){
          MMA16816(acc[mi][nj], a[mi], b[nj>>1][nj&1], b[nj>>1][(nj&1)+2]);
        }
      }
    }
    __syncthreads();
  }

  // epilogue
  const int mrow0 = bm + wm*64 + (lane>>2);
  const int ncol0 = bn + wn*32 + (lane&3)*2;
  #pragma unroll
  for(int mi=0;mi<4;mi++){
    int m0 = mrow0 + mi*16;
    #pragma unroll
    for(int nj=0;nj<4;nj++){
      int n0 = ncol0 + nj*8;
      float* c0 = C + (size_t)m0*ldc;
      float* c1 = C + (size_t)(m0+8)*ldc;
      if(Res){
        const float* r0 = Res + (size_t)m0*ldc;
        const float* r1 = Res + (size_t)(m0+8)*ldc;
        if(n0   < Nreal){ c0[n0]   = acc[mi][nj][0] + r0[n0];
                          c1[n0]   = acc[mi][nj][2] + r1[n0]; }
        if(n0+1 < Nreal){ c0[n0+1] = acc[mi][nj][1] + r0[n0+1];
                          c1[n0+1] = acc[mi][nj][3] + r1[n0+1]; }
      }else{
        if(n0   < Nreal){ c0[n0]   = acc[mi][nj][0];
                          c1[n0]   = acc[mi][nj][2]; }
        if(n0+1 < Nreal){ c0[n0+1] = acc[mi][nj][1];
                          c1[n0+1] = acc[mi][nj][3]; }
      }
    }
  }
}

// ---------------- SSD kernels ----------------
__global__ void k_conv(const float* __restrict__ cw, const float* __restrict__ cb,
                       const float* __restrict__ dtb, const float* __restrict__ alog){
  int row = blockIdx.x; int b = row/LL, t = row%LL;
  int tid = threadIdx.x;
  #pragma unroll
  for(int j=0;j<4;j++){
    int ch = tid + j*256;
    float acc = cb[ch];
    #pragma unroll
    for(int k=0;k<4;k++){
      int tt = t-3+k;
      if(tt>=0) acc += g_zx[(size_t)(b*LL+tt)*DPJ + DIN + ch]*cw[ch*4+k];
    }
    g_xBC[(size_t)row*CVD + ch] = acc/(1.f+expf(-acc));
  }
  if(tid < NHD){
    float v = g_zx[(size_t)row*DPJ + DIN + CVD + tid] + dtb[tid];
    float dtv = fmaxf(v,0.f) + log1pf(expf(-fabsf(v)));
    g_dt[row*NHD+tid] = dtv;
    g_dA[row*NHD+tid] = -expf(alog[tid])*dtv;
  }
}

__global__ void k_cumsum(){
  int bc = blockIdx.x; int h = threadIdx.x;
  if(h >= NHD) return;
  int b = bc/NCH, c = bc%NCH;
  float s = 0.f;
  for(int l=0;l<CHKL;l++){
    s += g_dA[(size_t)(b*LL + c*CHKL + l)*NHD + h];
    g_Acs[(bc*NHD+h)*CHKL + l] = s;
  }
  g_T[bc*NHD+h] = s;
}

__global__ void __launch_bounds__(256) k_cb(){
  int bc = blockIdx.x; int b = bc/NCH, c = bc%NCH;
  __shared__ float Cs[CHKL][65];
  __shared__ float Bs[CHKL][65];
  size_t rowb = (size_t)(b*LL + c*CHKL);
  int tid = threadIdx.x, tr = tid>>4, tc = tid&15;
  float acc[4][4];
  #pragma unroll
  for(int i=0;i<4;i++)
    #pragma unroll
    for(int j=0;j<4;j++) acc[i][j]=0.f;
  for(int n0=0;n0<DST;n0+=64){
    #pragma unroll
    for(int i=0;i<16;i++){
      int idx = tid + i*256; int l = idx>>6, k = idx&63;
      Cs[l][k] = g_xBC[(rowb+l)*CVD + DIN+DST + n0 + k];
      Bs[l][k] = g_xBC[(rowb+l)*CVD + DIN + n0 + k];
    }
    __syncthreads();
    #pragma unroll 8
    for(int k=0;k<64;k++){
      float a[4], bb[4];
      #pragma unroll
      for(int i=0;i<4;i++) a[i] = Cs[tr*4+i][k];
      #pragma unroll
      for(int j=0;j<4;j++) bb[j] = Bs[tc*4+j][k];
      #pragma unroll
      for(int i=0;i<4;i++)
        #pragma unroll
        for(int j=0;j<4;j++) acc[i][j] += a[i]*bb[j];
    }
    __syncthreads();
  }
  size_t ob = (size_t)bc*CHKL*CHKL;
  #pragma unroll
  for(int i=0;i<4;i++)
    #pragma unroll
    for(int j=0;j<4;j++)
      g_CB[ob + (tr*4+i)*64 + tc*4+j] = acc[i][j];
}

__global__ void __launch_bounds__(256) k_chunkstate(){
  int bc = blockIdx.x, h = blockIdx.y;
  int b = bc/NCH, c = bc%NCH;
  __shared__ float xsh[CHKL][HPD];
  __shared__ float coef[CHKL];
  size_t rowb = (size_t)(b*LL + c*CHKL);
  int tid = threadIdx.x;
  #pragma unroll
  for(int i=0;i<16;i++){
    int idx = tid + i*256; int l = idx>>6, p = idx&63;
    xsh[l][p] = g_xBC[(rowb+l)*CVD + h*HPD + p];
  }
  if(tid < CHKL){
    float T = g_T[bc*NHD+h];
    coef[tid] = expf(T - g_Acs[(bc*NHD+h)*CHKL + tid]) * g_dt[(rowb+tid)*NHD + h];
  }
  __syncthreads();
  int n = tid;
  float acc[HPD];
  #pragma unroll
  for(int p=0;p<HPD;p++) acc[p]=0.f;
  for(int l=0;l<CHKL;l++){
    float bv = g_xBC[(rowb+l)*CVD + DIN + n] * coef[l];
    #pragma unroll
    for(int p=0;p<HPD;p++) acc[p] += bv * xsh[l][p];
  }
  size_t base = ((size_t)bc*NHD + h)*(size_t)HPD*DST;
  #pragma unroll
  for(int p=0;p<HPD;p++) g_state[base + (size_t)p*DST + n] = acc[p];
}

__global__ void k_scan(){
  int bh = blockIdx.y; int b = bh>>3, h = bh&7;
  int idx = blockIdx.x*256 + threadIdx.x;
  float run = 0.f;
  for(int c=0;c<NCH;c++){
    size_t off = (((size_t)(b*NCH+c)*NHD + h)*(size_t)HPD*DST) + idx;
    float s = g_state[off];
    g_state[off] = run;
    run = run*expf(g_T[(b*NCH+c)*NHD + h]) + s;
  }
}

__global__ void __launch_bounds__(256) k_y(const float* __restrict__ Dp){
  extern __shared__ float sm[];
  float* xsh = sm;                       // 64*64
  float* cbl = sm + 4096;                // 64*65
  float* st  = sm + 4096 + 4160;         // 256*68
  float* cme = sm + 4096 + 4160 + 17408; // 64*257
  __shared__ float acs_s[64], dtl_s[64];
  int bc = blockIdx.x, h = blockIdx.y;
  int b = bc/NCH, c = bc%NCH;
  size_t rowb = (size_t)(b*LL + c*CHKL);
  int tid = threadIdx.x;
  if(tid < 64){
    acs_s[tid] = g_Acs[(bc*NHD+h)*CHKL + tid];
    dtl_s[tid] = g_dt[(rowb+tid)*NHD + h];
  }
  __syncthreads();
  #pragma unroll
  for(int i=0;i<16;i++){
    int idx = tid + i*256; int l = idx>>6, p = idx&63;
    xsh[idx] = g_xBC[(rowb+l)*CVD + h*HPD + p];
  }
  #pragma unroll
  for(int i=0;i<16;i++){
    int idx = tid + i*256; int l = idx>>6, s = idx&63;
    cbl[l*65+s] = (s<=l) ? g_CB[(size_t)bc*4096 + idx]*expf(acs_s[l]-acs_s[s])*dtl_s[s] : 0.f;
  }
  size_t stb = ((size_t)bc*NHD + h)*(size_t)HPD*DST;
  #pragma unroll
  for(int i=0;i<64;i++){
    int idx = tid + i*256; int p = idx>>8, n = idx&255;
    st[n*68+p] = g_state[stb + idx];
  }
  #pragma unroll
  for(int i=0;i<64;i++){
    int idx = tid + i*256; int l = idx>>8, n = idx&255;
    cme[l*257+n] = g_xBC[(rowb+l)*CVD + DIN+DST + n]*expf(acs_s[l]);
  }
  __syncthreads();

  int l = tid>>2, p0 = (tid&3)<<4;
  float acc[16];
  #pragma unroll
  for(int i=0;i<16;i++) acc[i]=0.f;
  for(int s=0;s<=l;s++){
    float cv = cbl[l*65+s];
    const float4* xr = (const float4*)&xsh[s*64+p0];
    #pragma unroll
    for(int q=0;q<4;q++){
      float4 xv = xr[q];
      acc[q*4+0] += cv*xv.x; acc[q*4+1] += cv*xv.y;
      acc[q*4+2] += cv*xv.z; acc[q*4+3] += cv*xv.w;
    }
  }
  #pragma unroll 4
  for(int n=0;n<DST;n++){
    float cv = cme[l*257+n];
    const float4* sr = (const float4*)&st[n*68+p0];
    #pragma unroll
    for(int q=0;q<4;q++){
      float4 sv = sr[q];
      acc[q*4+0] += cv*sv.x; acc[q*4+1] += cv*sv.y;
      acc[q*4+2] += cv*sv.z; acc[q*4+3] += cv*sv.w;
    }
  }
  float Dh = Dp[h];
  const float* xo = &xsh[l*64+p0];
  float* yo = &g_y[(rowb+l)*DIN + h*HPD + p0];
  #pragma unroll
  for(int i=0;i<16;i++) yo[i] = acc[i] + Dh*xo[i];
}

// ---------------- launch ----------------
extern "C" void kernel_launch(void* const* d_in, const int* in_sizes, int n_in,
                              void* d_out, int out_size){
  const float* x    = (const float*)d_in[0];
  const float* emb  = (const float*)d_in[1];
  const float* inw  = (const float*)d_in[2];
  const float* cw   = (const float*)d_in[3];
  const float* cb   = (const float*)d_in[4];
  const float* dtb  = (const float*)d_in[5];
  const float* alog = (const float*)d_in[6];
  const float* Dp   = (const float*)d_in[7];
  const float* gw   = (const float*)d_in[8];
  const float* ow   = (const float*)d_in[9];
  const float* nw   = (const float*)d_in[10];
  const float* nfw  = (const float*)d_in[11];
  const float* hw   = (const float*)d_in[12];
  float* out = (float*)d_out;

  float *ph, *pzx;
  __nv_bfloat16 *pab, *pwb;
  cudaGetSymbolAddress((void**)&ph,  g_h);
  cudaGetSymbolAddress((void**)&pzx, g_zx);
  cudaGetSymbolAddress((void**)&pab, g_Ab);
  cudaGetSymbolAddress((void**)&pwb, g_Wb);
  cudaFuncSetAttribute(k_y, cudaFuncAttributeMaxDynamicSharedMemorySize, 168448);
  cudaFuncSetAttribute(k_mgemm, cudaFuncAttributeMaxDynamicSharedMemorySize, 65536);

  k_embed<<<ROWS,256>>>(x, emb);
  for(int i=0;i<2;i++){
    k_rmsnorm_b<<<ROWS,256>>>(ph, nw + i*EMBD);
    k_prep_w<<<(NPAD_IN*768+255)/256,256>>>(inw + (size_t)i*EMBD*DPJ, 256, DPJ, NPAD_IN);
    k_mgemm<<<dim3(13,64),256,65536>>>(pab, pwb, pzx, nullptr, 768, DPJ, DPJ);
    k_conv<<<ROWS,256>>>(cw + i*CVD*4, cb + i*CVD, dtb + i*NHD, alog + i*NHD);
    k_cumsum<<<BB*NCH,32>>>();
    k_cb<<<BB*NCH,256>>>();
    k_chunkstate<<<dim3(BB*NCH,NHD),256>>>();
    k_scan<<<dim3(64,BB*NHD),256>>>();
    k_y<<<dim3(BB*NCH,NHD),256,168448>>>(Dp + i*NHD);
    k_gatednorm_b<<<ROWS,256>>>(gw + i*DIN);
    k_prep_w<<<(256*1536+255)/256,256>>>(ow + (size_t)i*DIN*EMBD, 512, EMBD, 256);
    k_mgemm<<<dim3(2,64),256,65536>>>(pab, pwb, ph, ph, 1536, EMBD, EMBD);
  }
  k_rmsnorm_b<<<ROWS,256>>>(ph, nfw);
  k_prep_w<<<(256*768+255)/256,256>>>(hw, 256, 256, 256);
  k_mgemm<<<dim3(2,64),256,65536>>>(pab, pwb, out, nullptr, 768, 256, 256);
}

// round 7
// speedup vs baseline: 1.6073x; 1.2910x over previous
#include <cuda_runtime.h>
#include <cuda_bf16.h>
#include <math.h>
#include <stdint.h>

#define BB 4
#define LL 2048
#define EMBD 256
#define NHD 8
#define HPD 64
#define DST 256
#define DIN 512
#define CVD 1024
#define DPJ 1544
#define CHKL 64
#define NCH 32
#define ROWS (BB*LL)
#define NPAD_IN 1664
#define NBC (BB*NCH)   // 128

// ---------------- scratch (static device globals; no allocation) ----------------
__device__ float g_h[ROWS*EMBD];
__device__ float g_zx[(size_t)ROWS*DPJ];
__device__ float g_xBC[(size_t)ROWS*CVD];
__device__ float g_dt[ROWS*NHD];
__device__ float g_dA[ROWS*NHD];
__device__ float g_Acs[NBC*NHD*CHKL];
__device__ float g_T[NBC*NHD];
__device__ float g_CB[NBC*CHKL*CHKL];
__device__ float g_state[(size_t)NBC*NHD*HPD*DST]; // [(bc*8+h)*64+p][n]
__device__ float g_y[(size_t)ROWS*DIN];
__device__ __nv_bfloat16 g_Ab[(size_t)ROWS*1536];     // activations, split-bf16, K3-major
__device__ __nv_bfloat16 g_Wb[(size_t)NPAD_IN*1536];  // weights, [n][K3]
__device__ __nv_bfloat16 g_Bsp[(size_t)ROWS*768];     // [Bh|Bl|Bh] per row
__device__ __nv_bfloat16 g_Csp[(size_t)ROWS*768];     // [Ch|Ch|Cl]
__device__ __nv_bfloat16 g_xdT[(size_t)NBC*512*192];  // [bc*512+h*64+p][Xh|Xh|Xl] over l
__device__ __nv_bfloat16 g_xdecT[(size_t)NBC*512*192];// xd*decay, [Xh|Xh|Xl]
__device__ __nv_bfloat16 g_BT[(size_t)NBC*256*192];   // [bc*256+n][Bh|Bl|Bh] over l

// ---------------- helpers ----------------
__device__ __forceinline__ uint32_t smem_u32(const void* p){
  uint32_t a;
  asm("{ .reg .u64 t; cvta.to.shared.u64 t, %1; cvt.u32.u64 %0, t; }" : "=r"(a) : "l"(p));
  return a;
}
__device__ __forceinline__ float blkReduce(float v, float* sh){
  int lane = threadIdx.x & 31, w = threadIdx.x >> 5;
  #pragma unroll
  for(int o=16;o;o>>=1) v += __shfl_xor_sync(0xffffffffu, v, o);
  if(lane==0) sh[w]=v;
  __syncthreads();
  float r = (threadIdx.x < 8) ? sh[threadIdx.x] : 0.f;
  if(w==0){
    #pragma unroll
    for(int o=4;o;o>>=1) r += __shfl_xor_sync(0xffffffffu, r, o);
    if(lane==0) sh[0]=r;
  }
  __syncthreads();
  return sh[0];
}

#define CPA16(sm, gp) \
  asm volatile("cp.async.cg.shared.global [%0], [%1], 16;" :: "r"(sm), "l"(gp))
#define CPA_COMMIT() asm volatile("cp.async.commit_group;" ::: "memory")
#define CPA_WAIT0()  asm volatile("cp.async.wait_group 0;" ::: "memory")
#define LDSM4(r0,r1,r2,r3,addr) \
  asm volatile("ldmatrix.sync.aligned.m8n8.x4.shared.b16 {%0,%1,%2,%3}, [%4];" \
    : "=r"(r0),"=r"(r1),"=r"(r2),"=r"(r3) : "r"(addr))
#define MMA16816(d, a, b0, b1) \
  asm volatile("mma.sync.aligned.m16n8k16.row.col.f32.bf16.bf16.f32 " \
    "{%0,%1,%2,%3}, {%4,%5,%6,%7}, {%8,%9}, {%0,%1,%2,%3};" \
    : "+f"((d)[0]),"+f"((d)[1]),"+f"((d)[2]),"+f"((d)[3]) \
    : "r"((a)[0]),"r"((a)[1]),"r"((a)[2]),"r"((a)[3]), "r"(b0),"r"(b1))

__device__ __forceinline__ uint32_t pack_bf2(__nv_bfloat16 a, __nv_bfloat16 b){
  return (uint32_t)__bfloat16_as_ushort(a) | ((uint32_t)__bfloat16_as_ushort(b)<<16);
}

// ---------------- elementwise kernels ----------------
__global__ void k_embed(const float* __restrict__ x, const float* __restrict__ emb){
  int row = blockIdx.x;
  float xv = x[row];
  int idx = (int)(255.0f * xv);
  idx = min(max(idx,0),255);
  g_h[(size_t)row*EMBD + threadIdx.x] = emb[(size_t)idx*EMBD + threadIdx.x];
}

__global__ void k_rmsnorm_b(const float* __restrict__ in, const float* __restrict__ w){
  __shared__ float sh[32];
  int row = blockIdx.x;
  float v = in[(size_t)row*EMBD + threadIdx.x];
  float s = blkReduce(v*v, sh);
  float sc = rsqrtf(s/(float)EMBD + 1e-5f);
  float o = v*sc*w[threadIdx.x];
  __nv_bfloat16 h = __float2bfloat16(o);
  __nv_bfloat16 l = __float2bfloat16(o - __bfloat162float(h));
  size_t b = (size_t)row*768 + threadIdx.x;
  g_Ab[b] = h; g_Ab[b+256] = h; g_Ab[b+512] = l;
}

__global__ void k_gatednorm_b(const float* __restrict__ gw){
  __shared__ float sh[32];
  int row = blockIdx.x;
  int i0 = threadIdx.x, i1 = threadIdx.x + 256;
  float z0 = g_zx[(size_t)row*DPJ + i0], y0 = g_y[(size_t)row*DIN + i0];
  float z1 = g_zx[(size_t)row*DPJ + i1], y1 = g_y[(size_t)row*DIN + i1];
  float v0 = y0 * (z0/(1.f+expf(-z0)));
  float v1 = y1 * (z1/(1.f+expf(-z1)));
  float s = blkReduce(v0*v0 + v1*v1, sh);
  float sc = rsqrtf(s/(float)DIN + 1e-5f);
  float o0 = v0*sc*gw[i0];
  float o1 = v1*sc*gw[i1];
  size_t b = (size_t)row*1536;
  __nv_bfloat16 h0 = __float2bfloat16(o0);
  __nv_bfloat16 l0 = __float2bfloat16(o0 - __bfloat162float(h0));
  __nv_bfloat16 h1 = __float2bfloat16(o1);
  __nv_bfloat16 l1 = __float2bfloat16(o1 - __bfloat162float(h1));
  g_Ab[b+i0] = h0; g_Ab[b+512+i0] = h0; g_Ab[b+1024+i0] = l0;
  g_Ab[b+i1] = h1; g_Ab[b+512+i1] = h1; g_Ab[b+1024+i1] = l1;
}

__global__ void k_prep_w(const float* __restrict__ W, int K, int N, int Npad){
  int K3 = K*3;
  int j = blockIdx.x*256 + threadIdx.x;
  if(j >= Npad*K3) return;
  int n = j / K3, r = j - n*K3;
  int seg = r / K, k = r - seg*K;
  __nv_bfloat16 v = __float2bfloat16(0.f);
  if(n < N){
    float w = W[(size_t)k*N + n];
    __nv_bfloat16 h = __float2bfloat16(w);
    if(seg==1) h = __float2bfloat16(w - __bfloat162float(h));
    v = h;
  }
  g_Wb[(size_t)n*K3 + r] = v;
}

// ---------------- warp-MMA bf16 GEMM (dense projections) ----------------
__global__ void __launch_bounds__(256,2) k_mgemm(
    const __nv_bfloat16* __restrict__ A, const __nv_bfloat16* __restrict__ Bw,
    float* __restrict__ C, const float* __restrict__ Res, int K3, int ldc, int Nreal)
{
  extern __shared__ __align__(1024) uint8_t smem[];
  const int tid = threadIdx.x;
  const int lane = tid & 31, wid = tid >> 5;
  const int wm = wid >> 2, wn = wid & 3;
  const int bm = blockIdx.y << 7, bn = blockIdx.x << 7;
  const uint32_t sbase = smem_u32(smem);

  uint32_t sw_off[4];
  const __nv_bfloat16 *ga[4], *gb[4];
  #pragma unroll
  for(int i=0;i<4;i++){
    int idx = tid + i*256, row = idx>>3, seg = idx&7;
    uint32_t off = (uint32_t)(row*128 + seg*16);
    sw_off[i] = off ^ ((off>>3)&0x70u);
    ga[i] = A  + (size_t)(bm+row)*K3 + seg*8;
    gb[i] = Bw + (size_t)(bn+row)*K3 + seg*8;
  }
  uint32_t arow[4], axb[4], brow[2], bxb[2];
  const uint32_t half16 = (uint32_t)(lane>>4)*16u;
  #pragma unroll
  for(int mi=0;mi<4;mi++){
    uint32_t r = (uint32_t)(wm*64 + mi*16 + (lane&15));
    arow[mi] = r*128u; axb[mi] = (arow[mi]>>3)&0x70u;
  }
  #pragma unroll
  for(int ni=0;ni<2;ni++){
    uint32_t r = (uint32_t)(wn*32 + ni*16 + (lane&15));
    brow[ni] = r*128u; bxb[ni] = (brow[ni]>>3)&0x70u;
  }
  float acc[4][4][4];
  #pragma unroll
  for(int i=0;i<4;i++)
    #pragma unroll
    for(int j=0;j<4;j++)
      #pragma unroll
      for(int q=0;q<4;q++) acc[i][j][q]=0.f;

  const int NC = K3 >> 6;
  {
    #pragma unroll
    for(int i=0;i<4;i++){
      CPA16(sbase + sw_off[i],         ga[i]);
      CPA16(sbase + 32768 + sw_off[i], gb[i]);
    }
    CPA_COMMIT();
  }
  for(int c=0;c<NC;c++){
    CPA_WAIT0();
    __syncthreads();
    if(c+1 < NC){
      uint32_t st = (uint32_t)((c+1)&1)*16384u;
      int k0 = (c+1)<<6;
      #pragma unroll
      for(int i=0;i<4;i++){
        CPA16(sbase + st + sw_off[i],         ga[i] + k0);
        CPA16(sbase + 32768 + st + sw_off[i], gb[i] + k0);
      }
      CPA_COMMIT();
    }
    const uint32_t sa = sbase + (uint32_t)(c&1)*16384u;
    const uint32_t sb = sa + 32768u;
    #pragma unroll
    for(int s=0;s<4;s++){
      const uint32_t col = (uint32_t)(s*32) + half16;
      uint32_t a[4][4], b[2][4];
      #pragma unroll
      for(int mi=0;mi<4;mi++)
        LDSM4(a[mi][0],a[mi][1],a[mi][2],a[mi][3], sa + arow[mi] + (col ^ axb[mi]));
      #pragma unroll
      for(int ni=0;ni<2;ni++)
        LDSM4(b[ni][0],b[ni][1],b[ni][2],b[ni][3], sb + brow[ni] + (col ^ bxb[ni]));
      #pragma unroll
      for(int mi=0;mi<4;mi++)
        #pragma unroll
        for(int nj=0;nj<4;nj++)
          MMA16816(acc[mi][nj], a[mi], b[nj>>1][nj&1], b[nj>>1][(nj&1)+2]);
    }
    __syncthreads();
  }
  const int mrow0 = bm + wm*64 + (lane>>2);
  const int ncol0 = bn + wn*32 + (lane&3)*2;
  #pragma unroll
  for(int mi=0;mi<4;mi++){
    int m0 = mrow0 + mi*16;
    #pragma unroll
    for(int nj=0;nj<4;nj++){
      int n0 = ncol0 + nj*8;
      float* c0 = C + (size_t)m0*ldc;
      float* c1 = C + (size_t)(m0+8)*ldc;
      if(Res){
        const float* r0 = Res + (size_t)m0*ldc;
        const float* r1 = Res + (size_t)(m0+8)*ldc;
        if(n0   < Nreal){ c0[n0]   = acc[mi][nj][0] + r0[n0];
                          c1[n0]   = acc[mi][nj][2] + r1[n0]; }
        if(n0+1 < Nreal){ c0[n0+1] = acc[mi][nj][1] + r0[n0+1];
                          c1[n0+1] = acc[mi][nj][3] + r1[n0+1]; }
      }else{
        if(n0   < Nreal){ c0[n0]   = acc[mi][nj][0];
                          c1[n0]   = acc[mi][nj][2]; }
        if(n0+1 < Nreal){ c0[n0+1] = acc[mi][nj][1];
                          c1[n0+1] = acc[mi][nj][3]; }
      }
    }
  }
}

// ---------------- conv + SiLU + dt + B/C split emission ----------------
__global__ void k_conv(const float* __restrict__ cw, const float* __restrict__ cb,
                       const float* __restrict__ dtb, const float* __restrict__ alog){
  int row = blockIdx.x; int b = row/LL, t = row%LL;
  int tid = threadIdx.x;
  #pragma unroll
  for(int j=0;j<4;j++){
    int ch = tid + j*256;
    float acc = cb[ch];
    #pragma unroll
    for(int k=0;k<4;k++){
      int tt = t-3+k;
      if(tt>=0) acc += g_zx[(size_t)(b*LL+tt)*DPJ + DIN + ch]*cw[ch*4+k];
    }
    float v = acc/(1.f+expf(-acc));
    g_xBC[(size_t)row*CVD + ch] = v;
    if(j==2){ // B part
      int n = ch - 512;
      __nv_bfloat16 h = __float2bfloat16(v);
      __nv_bfloat16 l = __float2bfloat16(v - __bfloat162float(h));
      size_t o = (size_t)row*768 + n;
      g_Bsp[o] = h; g_Bsp[o+256] = l; g_Bsp[o+512] = h;
    } else if(j==3){ // C part
      int n = ch - 768;
      __nv_bfloat16 h = __float2bfloat16(v);
      __nv_bfloat16 l = __float2bfloat16(v - __bfloat162float(h));
      size_t o = (size_t)row*768 + n;
      g_Csp[o] = h; g_Csp[o+256] = h; g_Csp[o+512] = l;
    }
  }
  if(tid < NHD){
    float v = g_zx[(size_t)row*DPJ + DIN + CVD + tid] + dtb[tid];
    float dtv = fmaxf(v,0.f) + log1pf(expf(-fabsf(v)));
    g_dt[row*NHD+tid] = dtv;
    g_dA[row*NHD+tid] = -expf(alog[tid])*dtv;
  }
}

__global__ void k_cumsum(){
  int bc = blockIdx.x; int h = threadIdx.x;
  if(h >= NHD) return;
  float s = 0.f;
  size_t rowb = (size_t)bc*CHKL;
  for(int l=0;l<CHKL;l++){
    s += g_dA[(rowb + l)*NHD + h];
    g_Acs[(bc*NHD+h)*CHKL + l] = s;
  }
  g_T[bc*NHD+h] = s;
}

// ---------------- transpose prep: xdT, xdecT, BT ----------------
__global__ void __launch_bounds__(256) k_trans(){
  int bc = blockIdx.x;
  __shared__ float tile[64][65];
  __shared__ float acs8[8][64];
  __shared__ float dt8[64][8];
  __shared__ float T8[8];
  __shared__ float dec[64];
  int tid = threadIdx.x;
  size_t rowb = (size_t)bc*64;
  #pragma unroll
  for(int i=0;i<2;i++){
    int idx = tid + i*256;
    acs8[idx>>6][idx&63] = g_Acs[bc*512 + idx];
    dt8[idx>>3][idx&7]   = g_dt[(rowb + (idx>>3))*8 + (idx&7)];
  }
  if(tid < 8) T8[tid] = g_T[bc*8 + tid];
  __syncthreads();

  int oc = tid>>2, lq = (tid&3)<<4;
  for(int t=0;t<12;t++){
    int colbase = (t<8) ? t*64 : 512 + (t-8)*64;
    #pragma unroll
    for(int i=0;i<16;i++){
      int idx = tid + i*256;
      tile[idx>>6][idx&63] = g_xBC[(rowb + (idx>>6))*CVD + colbase + (idx&63)];
    }
    if(t<8 && tid<64) dec[tid] = expf(T8[t] - acs8[t][tid]);
    __syncthreads();
    if(t<8){
      union { __nv_bfloat16 h[16]; uint4 u[2]; } H, L, Hd, Ld;
      #pragma unroll
      for(int li=0;li<16;li++){
        int l = lq+li;
        float xv = tile[l][oc]*dt8[l][t];
        __nv_bfloat16 h = __float2bfloat16(xv);
        H.h[li] = h; L.h[li] = __float2bfloat16(xv - __bfloat162float(h));
        float xd = xv*dec[l];
        __nv_bfloat16 hd = __float2bfloat16(xd);
        Hd.h[li] = hd; Ld.h[li] = __float2bfloat16(xd - __bfloat162float(hd));
      }
      size_t b0 = ((size_t)bc*512 + t*64 + oc)*192;
      uint4* d0 = (uint4*)(g_xdT + b0 + lq);
      uint4* d1 = (uint4*)(g_xdT + b0 + 64 + lq);
      uint4* d2 = (uint4*)(g_xdT + b0 + 128 + lq);
      d0[0]=H.u[0]; d0[1]=H.u[1]; d1[0]=H.u[0]; d1[1]=H.u[1]; d2[0]=L.u[0]; d2[1]=L.u[1];
      uint4* e0 = (uint4*)(g_xdecT + b0 + lq);
      uint4* e1 = (uint4*)(g_xdecT + b0 + 64 + lq);
      uint4* e2 = (uint4*)(g_xdecT + b0 + 128 + lq);
      e0[0]=Hd.u[0]; e0[1]=Hd.u[1]; e1[0]=Hd.u[0]; e1[1]=Hd.u[1]; e2[0]=Ld.u[0]; e2[1]=Ld.u[1];
    }else{
      union { __nv_bfloat16 h[16]; uint4 u[2]; } H, L;
      #pragma unroll
      for(int li=0;li<16;li++){
        int l = lq+li;
        float v = tile[l][oc];
        __nv_bfloat16 h = __float2bfloat16(v);
        H.h[li] = h; L.h[li] = __float2bfloat16(v - __bfloat162float(h));
      }
      size_t b0 = ((size_t)bc*256 + (t-8)*64 + oc)*192;
      uint4* d0 = (uint4*)(g_BT + b0 + lq);
      uint4* d1 = (uint4*)(g_BT + b0 + 64 + lq);
      uint4* d2 = (uint4*)(g_BT + b0 + 128 + lq);
      d0[0]=H.u[0]; d0[1]=H.u[1]; d1[0]=L.u[0]; d1[1]=L.u[1]; d2[0]=H.u[0]; d2[1]=H.u[1];
    }
    __syncthreads();
  }
}

// ---------------- CB = C * B^T via MMA (K=768 split) ----------------
__global__ void __launch_bounds__(128) k_cb_mma(){
  int bc = blockIdx.x;
  __shared__ __align__(1024) uint8_t sA[8192];
  __shared__ __align__(1024) uint8_t sB[8192];
  int tid = threadIdx.x, lane = tid&31, wid = tid>>5;
  int wm = wid>>1, wn = wid&1;
  uint32_t aA = smem_u32(sA), aB = smem_u32(sB);
  size_t rowb = (size_t)bc*64;
  const __nv_bfloat16* A = g_Csp + rowb*768;
  const __nv_bfloat16* B = g_Bsp + rowb*768;

  float acc[2][4][4];
  #pragma unroll
  for(int i=0;i<2;i++)
    #pragma unroll
    for(int j=0;j<4;j++)
      #pragma unroll
      for(int q=0;q<4;q++) acc[i][j][q]=0.f;

  const uint32_t half16 = (uint32_t)(lane>>4)*16u;
  uint32_t arow[2], axb[2], brow[2], bxb[2];
  #pragma unroll
  for(int mi=0;mi<2;mi++){
    uint32_t r = (uint32_t)(wm*32 + mi*16 + (lane&15));
    arow[mi]=r*128u; axb[mi]=(arow[mi]>>3)&0x70u;
  }
  #pragma unroll
  for(int ni=0;ni<2;ni++){
    uint32_t r = (uint32_t)(wn*32 + ni*16 + (lane&15));
    brow[ni]=r*128u; bxb[ni]=(brow[ni]>>3)&0x70u;
  }
  for(int ch=0;ch<12;ch++){
    int k0 = ch*64;
    #pragma unroll
    for(int i=0;i<4;i++){
      int v = tid + i*128, row = v>>3, seg = v&7;
      uint32_t off = (uint32_t)(row*128 + seg*16);
      off ^= (off>>3)&0x70u;
      CPA16(aA + off, A + (size_t)row*768 + k0 + seg*8);
      CPA16(aB + off, B + (size_t)row*768 + k0 + seg*8);
    }
    CPA_COMMIT(); CPA_WAIT0();
    __syncthreads();
    #pragma unroll
    for(int s=0;s<4;s++){
      uint32_t col = (uint32_t)(s*32) + half16;
      uint32_t a[2][4], b[2][4];
      #pragma unroll
      for(int mi=0;mi<2;mi++)
        LDSM4(a[mi][0],a[mi][1],a[mi][2],a[mi][3], aA + arow[mi] + (col ^ axb[mi]));
      #pragma unroll
      for(int ni=0;ni<2;ni++)
        LDSM4(b[ni][0],b[ni][1],b[ni][2],b[ni][3], aB + brow[ni] + (col ^ bxb[ni]));
      #pragma unroll
      for(int mi=0;mi<2;mi++)
        #pragma unroll
        for(int nj=0;nj<4;nj++)
          MMA16816(acc[mi][nj], a[mi], b[nj>>1][nj&1], b[nj>>1][(nj&1)+2]);
    }
    __syncthreads();
  }
  float* CB = g_CB + (size_t)bc*4096;
  #pragma unroll
  for(int mi=0;mi<2;mi++){
    int m0 = wm*32 + mi*16 + (lane>>2);
    #pragma unroll
    for(int nj=0;nj<4;nj++){
      int n0 = wn*32 + nj*8 + (lane&3)*2;
      CB[m0*64+n0]     = acc[mi][nj][0];
      CB[m0*64+n0+1]   = acc[mi][nj][1];
      CB[(m0+8)*64+n0]   = acc[mi][nj][2];
      CB[(m0+8)*64+n0+1] = acc[mi][nj][3];
    }
  }
}

// ---------------- chunk state via MMA: state[p][n], K=192 ----------------
__global__ void __launch_bounds__(256) k_cs_mma(){
  int bc = blockIdx.x, h = blockIdx.y;
  __shared__ __align__(1024) uint8_t sA[8192];
  __shared__ __align__(1024) uint8_t sB[32768];
  int tid = threadIdx.x, lane = tid&31, wid = tid>>5;
  int wm = wid>>2, wn = wid&3;
  uint32_t aA = smem_u32(sA), aB = smem_u32(sB);
  const __nv_bfloat16* A = g_xdecT + ((size_t)bc*512 + h*64)*192;
  const __nv_bfloat16* B = g_BT + (size_t)bc*256*192;

  float acc[2][8][4];
  #pragma unroll
  for(int i=0;i<2;i++)
    #pragma unroll
    for(int j=0;j<8;j++)
      #pragma unroll
      for(int q=0;q<4;q++) acc[i][j][q]=0.f;

  const uint32_t half16 = (uint32_t)(lane>>4)*16u;
  uint32_t arow[2], axb[2], brow[4], bxb[4];
  #pragma unroll
  for(int mi=0;mi<2;mi++){
    uint32_t r = (uint32_t)(wm*32 + mi*16 + (lane&15));
    arow[mi]=r*128u; axb[mi]=(arow[mi]>>3)&0x70u;
  }
  #pragma unroll
  for(int ni=0;ni<4;ni++){
    uint32_t r = (uint32_t)(wn*64 + ni*16 + (lane&15));
    brow[ni]=r*128u; bxb[ni]=(brow[ni]>>3)&0x70u;
  }
  for(int ch=0;ch<3;ch++){
    int k0 = ch*64;
    #pragma unroll
    for(int i=0;i<2;i++){
      int v = tid + i*256, row = v>>3, seg = v&7;
      uint32_t off = (uint32_t)(row*128 + seg*16);
      off ^= (off>>3)&0x70u;
      CPA16(aA + off, A + (size_t)row*192 + k0 + seg*8);
    }
    #pragma unroll
    for(int i=0;i<8;i++){
      int v = tid + i*256, row = v>>3, seg = v&7;
      uint32_t off = (uint32_t)(row*128 + seg*16);
      off ^= (off>>3)&0x70u;
      CPA16(aB + off, B + (size_t)row*192 + k0 + seg*8);
    }
    CPA_COMMIT(); CPA_WAIT0();
    __syncthreads();
    #pragma unroll
    for(int s=0;s<4;s++){
      uint32_t col = (uint32_t)(s*32) + half16;
      uint32_t a[2][4], b[4][4];
      #pragma unroll
      for(int mi=0;mi<2;mi++)
        LDSM4(a[mi][0],a[mi][1],a[mi][2],a[mi][3], aA + arow[mi] + (col ^ axb[mi]));
      #pragma unroll
      for(int ni=0;ni<4;ni++)
        LDSM4(b[ni][0],b[ni][1],b[ni][2],b[ni][3], aB + brow[ni] + (col ^ bxb[ni]));
      #pragma unroll
      for(int mi=0;mi<2;mi++)
        #pragma unroll
        for(int nj=0;nj<8;nj++)
          MMA16816(acc[mi][nj], a[mi], b[nj>>1][nj&1], b[nj>>1][(nj&1)+2]);
    }
    __syncthreads();
  }
  float* S = g_state + ((size_t)(bc*8+h)*64)*256;
  #pragma unroll
  for(int mi=0;mi<2;mi++){
    int m0 = wm*32 + mi*16 + (lane>>2);
    #pragma unroll
    for(int nj=0;nj<8;nj++){
      int n0 = wn*64 + nj*8 + (lane&3)*2;
      S[(size_t)m0*256+n0]       = acc[mi][nj][0];
      S[(size_t)m0*256+n0+1]     = acc[mi][nj][1];
      S[(size_t)(m0+8)*256+n0]   = acc[mi][nj][2];
      S[(size_t)(m0+8)*256+n0+1] = acc[mi][nj][3];
    }
  }
}

// ---------------- inter-chunk scan (fp32, exclusive prefix in place) ----------------
__global__ void k_scan(){
  int bh = blockIdx.y; int b = bh>>3, h = bh&7;
  int idx = blockIdx.x*256 + threadIdx.x;
  float run = 0.f;
  for(int c=0;c<NCH;c++){
    size_t off = (((size_t)(b*NCH+c)*NHD + h)*(size_t)HPD*DST) + idx;
    float s = g_state[off];
    g_state[off] = run;
    run = run*expf(g_T[(b*NCH+c)*NHD + h]) + s;
  }
}

// ---------------- Y via MMA: diag (K=192) + off (K=768) + D skip ----------------
__global__ void __launch_bounds__(128) k_y_mma(const float* __restrict__ Dp){
  int bc = blockIdx.x, h = blockIdx.y;
  __shared__ float L[64][68];
  __shared__ float acs[64];
  __shared__ __align__(1024) uint8_t tA[8192];
  __shared__ __align__(1024) uint8_t tB[8192];
  int tid = threadIdx.x, lane = tid&31, wid = tid>>5;
  int wm = wid>>1, wn = wid&1;
  uint32_t aA = smem_u32(tA), aB = smem_u32(tB);
  size_t rowb = (size_t)bc*64;

  if(tid < 64) acs[tid] = g_Acs[(bc*8+h)*64 + tid];
  __syncthreads();
  #pragma unroll
  for(int i=0;i<32;i++){
    int idx = tid + i*128;
    int l = idx>>6, s = idx&63;
    L[l][s] = (s<=l) ? g_CB[(size_t)bc*4096 + idx]*expf(acs[l]-acs[s]) : 0.f;
  }

  float acc[2][4][4];
  #pragma unroll
  for(int i=0;i<2;i++)
    #pragma unroll
    for(int j=0;j<4;j++)
      #pragma unroll
      for(int q=0;q<4;q++) acc[i][j][q]=0.f;

  const uint32_t half16 = (uint32_t)(lane>>4)*16u;
  uint32_t arow[2], axb[2], brow[2], bxb[2];
  #pragma unroll
  for(int mi=0;mi<2;mi++){
    uint32_t r = (uint32_t)(wm*32 + mi*16 + (lane&15));
    arow[mi]=r*128u; axb[mi]=(arow[mi]>>3)&0x70u;
  }
  #pragma unroll
  for(int ni=0;ni<2;ni++){
    uint32_t r = (uint32_t)(wn*32 + ni*16 + (lane&15));
    brow[ni]=r*128u; bxb[ni]=(brow[ni]>>3)&0x70u;
  }

  // ---- phase B: C * state^T (K=768), exp(acs_l) factored out ----
  const __nv_bfloat16* Ag = g_Csp + rowb*768;
  const float* Sg = g_state + (size_t)(bc*8+h)*16384;
  __syncthreads();
  for(int j=0;j<12;j++){
    #pragma unroll
    for(int i=0;i<4;i++){
      int v = tid + i*128, row = v>>3, seg = v&7;
      uint32_t off = (uint32_t)(row*128 + seg*16);
      off ^= (off>>3)&0x70u;
      CPA16(aA + off, Ag + (size_t)row*768 + j*64 + seg*8);
    }
    int n0 = (j&3)*64;
    bool lov = ((j>>2)==1);
    #pragma unroll
    for(int i=0;i<8;i++){
      int v = tid + i*128;
      int p = v>>4, q = v&15;
      float4 f = *(const float4*)(Sg + (size_t)p*256 + n0 + q*4);
      __nv_bfloat16 c0,c1,c2,c3;
      if(lov){
        __nv_bfloat16 h0=__float2bfloat16(f.x), h1=__float2bfloat16(f.y),
                      h2=__float2bfloat16(f.z), h3=__float2bfloat16(f.w);
        c0=__float2bfloat16(f.x-__bfloat162float(h0));
        c1=__float2bfloat16(f.y-__bfloat162float(h1));
        c2=__float2bfloat16(f.z-__bfloat162float(h2));
        c3=__float2bfloat16(f.w-__bfloat162float(h3));
      }else{
        c0=__float2bfloat16(f.x); c1=__float2bfloat16(f.y);
        c2=__float2bfloat16(f.z); c3=__float2bfloat16(f.w);
      }
      uint32_t byteoff = (uint32_t)(p*128 + q*8);
      byteoff ^= (byteoff>>3)&0x70u;
      *(uint2*)(tB + byteoff) = make_uint2(pack_bf2(c0,c1), pack_bf2(c2,c3));
    }
    CPA_COMMIT(); CPA_WAIT0();
    __syncthreads();
    #pragma unroll
    for(int s=0;s<4;s++){
      uint32_t col = (uint32_t)(s*32) + half16;
      uint32_t a[2][4], b[2][4];
      #pragma unroll
      for(int mi=0;mi<2;mi++)
        LDSM4(a[mi][0],a[mi][1],a[mi][2],a[mi][3], aA + arow[mi] + (col ^ axb[mi]));
      #pragma unroll
      for(int ni=0;ni<2;ni++)
        LDSM4(b[ni][0],b[ni][1],b[ni][2],b[ni][3], aB + brow[ni] + (col ^ bxb[ni]));
      #pragma unroll
      for(int mi=0;mi<2;mi++)
        #pragma unroll
        for(int nj=0;nj<4;nj++)
          MMA16816(acc[mi][nj], a[mi], b[nj>>1][nj&1], b[nj>>1][(nj&1)+2]);
    }
    __syncthreads();
  }
  // scale by exp(acs_l)
  #pragma unroll
  for(int mi=0;mi<2;mi++){
    int r0 = wm*32 + mi*16 + (lane>>2);
    float e0 = expf(acs[r0]), e1 = expf(acs[r0+8]);
    #pragma unroll
    for(int nj=0;nj<4;nj++){
      acc[mi][nj][0]*=e0; acc[mi][nj][1]*=e0;
      acc[mi][nj][2]*=e1; acc[mi][nj][3]*=e1;
    }
  }
  // ---- phase A: L * xd (K=192 split) ----
  const __nv_bfloat16* Bg = g_xdT + ((size_t)bc*512 + h*64)*192;
  for(int j=0;j<3;j++){
    #pragma unroll
    for(int i=0;i<4;i++){
      int v = tid + i*128, row = v>>3, seg = v&7;
      uint32_t off = (uint32_t)(row*128 + seg*16);
      off ^= (off>>3)&0x70u;
      CPA16(aB + off, Bg + (size_t)row*192 + j*64 + seg*8);
    }
    bool lov = (j==1);
    #pragma unroll
    for(int i=0;i<8;i++){
      int v = tid + i*128;
      int l = v>>4, q = v&15;
      float4 f = *(const float4*)(&L[l][q*4]);
      __nv_bfloat16 c0,c1,c2,c3;
      if(lov){
        __nv_bfloat16 h0=__float2bfloat16(f.x), h1=__float2bfloat16(f.y),
                      h2=__float2bfloat16(f.z), h3=__float2bfloat16(f.w);
        c0=__float2bfloat16(f.x-__bfloat162float(h0));
        c1=__float2bfloat16(f.y-__bfloat162float(h1));
        c2=__float2bfloat16(f.z-__bfloat162float(h2));
        c3=__float2bfloat16(f.w-__bfloat162float(h3));
      }else{
        c0=__float2bfloat16(f.x); c1=__float2bfloat16(f.y);
        c2=__float2bfloat16(f.z); c3=__float2bfloat16(f.w);
      }
      uint32_t byteoff = (uint32_t)(l*128 + q*8);
      byteoff ^= (byteoff>>3)&0x70u;
      *(uint2*)(tA + byteoff) = make_uint2(pack_bf2(c0,c1), pack_bf2(c2,c3));
    }
    CPA_COMMIT(); CPA_WAIT0();
    __syncthreads();
    #pragma unroll
    for(int s=0;s<4;s++){
      uint32_t col = (uint32_t)(s*32) + half16;
      uint32_t a[2][4], b[2][4];
      #pragma unroll
      for(int mi=0;mi<2;mi++)
        LDSM4(a[mi][0],a[mi][1],a[mi][2],a[mi][3], aA + arow[mi] + (col ^ axb[mi]));
      #pragma unroll
      for(int ni=0;ni<2;ni++)
        LDSM4(b[ni][0],b[ni][1],b[ni][2],b[ni][3], aB + brow[ni] + (col ^ bxb[ni]));
      #pragma unroll
      for(int mi=0;mi<2;mi++)
        #pragma unroll
        for(int nj=0;nj<4;nj++)
          MMA16816(acc[mi][nj], a[mi], b[nj>>1][nj&1], b[nj>>1][(nj&1)+2]);
    }
    __syncthreads();
  }
  // ---- epilogue: + D*xh ----
  float Dh = Dp[h];
  #pragma unroll
  for(int mi=0;mi<2;mi++){
    int l0 = wm*32 + mi*16 + (lane>>2);
    #pragma unroll
    for(int nj=0;nj<4;nj++){
      int p0 = wn*32 + nj*8 + (lane&3)*2;
      #pragma unroll
      for(int dl=0;dl<2;dl++){
        int l = l0 + dl*8;
        size_t xb = (rowb+l)*CVD + h*64;
        size_t yb = (rowb+l)*DIN + h*64;
        g_y[yb+p0]   = acc[mi][nj][dl*2+0] + Dh*g_xBC[xb+p0];
        g_y[yb+p0+1] = acc[mi][nj][dl*2+1] + Dh*g_xBC[xb+p0+1];
      }
    }
  }
}

// ---------------- launch ----------------
extern "C" void kernel_launch(void* const* d_in, const int* in_sizes, int n_in,
                              void* d_out, int out_size){
  const float* x    = (const float*)d_in[0];
  const float* emb  = (const float*)d_in[1];
  const float* inw  = (const float*)d_in[2];
  const float* cw   = (const float*)d_in[3];
  const float* cb   = (const float*)d_in[4];
  const float* dtb  = (const float*)d_in[5];
  const float* alog = (const float*)d_in[6];
  const float* Dp   = (const float*)d_in[7];
  const float* gw   = (const float*)d_in[8];
  const float* ow   = (const float*)d_in[9];
  const float* nw   = (const float*)d_in[10];
  const float* nfw  = (const float*)d_in[11];
  const float* hw   = (const float*)d_in[12];
  float* out = (float*)d_out;

  float *ph, *pzx;
  __nv_bfloat16 *pab, *pwb;
  cudaGetSymbolAddress((void**)&ph,  g_h);
  cudaGetSymbolAddress((void**)&pzx, g_zx);
  cudaGetSymbolAddress((void**)&pab, g_Ab);
  cudaGetSymbolAddress((void**)&pwb, g_Wb);
  cudaFuncSetAttribute(k_mgemm, cudaFuncAttributeMaxDynamicSharedMemorySize, 65536);

  k_embed<<<ROWS,256>>>(x, emb);
  for(int i=0;i<2;i++){
    k_rmsnorm_b<<<ROWS,256>>>(ph, nw + i*EMBD);
    k_prep_w<<<(NPAD_IN*768+255)/256,256>>>(inw + (size_t)i*EMBD*DPJ, 256, DPJ, NPAD_IN);
    k_mgemm<<<dim3(13,64),256,65536>>>(pab, pwb, pzx, nullptr, 768, DPJ, DPJ);
    k_conv<<<ROWS,256>>>(cw + i*CVD*4, cb + i*CVD, dtb + i*NHD, alog + i*NHD);
    k_cumsum<<<NBC,32>>>();
    k_trans<<<NBC,256>>>();
    k_cb_mma<<<NBC,128>>>();
    k_cs_mma<<<dim3(NBC,NHD),256>>>();
    k_scan<<<dim3(64,NCH),256>>>();
    k_y_mma<<<dim3(NBC,NHD),128>>>(Dp + i*NHD);
    k_gatednorm_b<<<ROWS,256>>>(gw + i*DIN);
    k_prep_w<<<(256*1536+255)/256,256>>>(ow + (size_t)i*DIN*EMBD, 512, EMBD, 256);
    k_mgemm<<<dim3(2,64),256,65536>>>(pab, pwb, ph, ph, 1536, EMBD, EMBD);
  }
  k_rmsnorm_b<<<ROWS,256>>>(ph, nfw);
  k_prep_w<<<(256*768+255)/256,256>>>(hw, 256, 256, 256);
  k_mgemm<<<dim3(2,64),256,65536>>>(pab, pwb, out, nullptr, 768, 256, 256);
}

// round 8
// speedup vs baseline: 2.9718x; 1.8489x over previous
#include <cuda_runtime.h>
#include <cuda_bf16.h>
#include <math.h>
#include <stdint.h>

#define BB 4
#define LL 2048
#define EMBD 256
#define NHD 8
#define HPD 64
#define DST 256
#define DIN 512
#define CVD 1024
#define DPJ 1544
#define CHKL 64
#define NCH 32
#define ROWS (BB*LL)
#define NPAD_IN 1664
#define NBC (BB*NCH)   // 128

// ---------------- scratch ----------------
__device__ float g_h[ROWS*EMBD];
__device__ float g_zx[(size_t)ROWS*DPJ];
__device__ float g_xBC[(size_t)ROWS*CVD];
__device__ float g_dt[ROWS*NHD];
__device__ float g_dA[ROWS*NHD];
__device__ float g_Acs[NBC*NHD*CHKL];
__device__ float g_T[NBC*NHD];
__device__ float g_CB[NBC*CHKL*CHKL];
__device__ float g_state[(size_t)NBC*NHD*HPD*DST];      // [(bc*8+h)*64+p][n] fp32
__device__ float g_y[(size_t)ROWS*DIN];
__device__ __nv_bfloat16 g_Ab[(size_t)ROWS*1536];
__device__ __nv_bfloat16 g_Wb[(size_t)NPAD_IN*1536];
__device__ __nv_bfloat16 g_Bsp[(size_t)ROWS*768];       // [Bh|Bl|Bh]
__device__ __nv_bfloat16 g_Csp[(size_t)ROWS*768];       // [Ch|Ch|Cl]
__device__ __nv_bfloat16 g_xdT[(size_t)NBC*512*192];    // x*dt transposed [Xh|Xh|Xl]
__device__ __nv_bfloat16 g_xdecT[(size_t)NBC*512*192];  // x*dt*decay [Xh|Xh|Xl]
__device__ __nv_bfloat16 g_BT[(size_t)NBC*256*192];     // B^T [Bh|Bl|Bh]
__device__ __nv_bfloat16 g_Ssp[(size_t)NBC*NHD*64*768]; // prefix state split [Sh|Sl|Sh]

// ---------------- helpers ----------------
__device__ __forceinline__ uint32_t smem_u32(const void* p){
  uint32_t a;
  asm("{ .reg .u64 t; cvta.to.shared.u64 t, %1; cvt.u32.u64 %0, t; }" : "=r"(a) : "l"(p));
  return a;
}
__device__ __forceinline__ float blkReduce(float v, float* sh){
  int lane = threadIdx.x & 31, w = threadIdx.x >> 5;
  #pragma unroll
  for(int o=16;o;o>>=1) v += __shfl_xor_sync(0xffffffffu, v, o);
  if(lane==0) sh[w]=v;
  __syncthreads();
  float r = (threadIdx.x < 8) ? sh[threadIdx.x] : 0.f;
  if(w==0){
    #pragma unroll
    for(int o=4;o;o>>=1) r += __shfl_xor_sync(0xffffffffu, r, o);
    if(lane==0) sh[0]=r;
  }
  __syncthreads();
  return sh[0];
}

#define CPA16(sm, gp) \
  asm volatile("cp.async.cg.shared.global [%0], [%1], 16;" :: "r"(sm), "l"(gp))
#define CPA_COMMIT() asm volatile("cp.async.commit_group;" ::: "memory")
#define CPA_WAIT0()  asm volatile("cp.async.wait_group 0;" ::: "memory")
#define LDSM4(r0,r1,r2,r3,addr) \
  asm volatile("ldmatrix.sync.aligned.m8n8.x4.shared.b16 {%0,%1,%2,%3}, [%4];" \
    : "=r"(r0),"=r"(r1),"=r"(r2),"=r"(r3) : "r"(addr))
#define MMA16816(d, a, b0, b1) \
  asm volatile("mma.sync.aligned.m16n8k16.row.col.f32.bf16.bf16.f32 " \
    "{%0,%1,%2,%3}, {%4,%5,%6,%7}, {%8,%9}, {%0,%1,%2,%3};" \
    : "+f"((d)[0]),"+f"((d)[1]),"+f"((d)[2]),"+f"((d)[3]) \
    : "r"((a)[0]),"r"((a)[1]),"r"((a)[2]),"r"((a)[3]), "r"(b0),"r"(b1))

__device__ __forceinline__ uint32_t pack_bf2(__nv_bfloat16 a, __nv_bfloat16 b){
  return (uint32_t)__bfloat16_as_ushort(a) | ((uint32_t)__bfloat16_as_ushort(b)<<16);
}

// ---------------- elementwise kernels ----------------
__global__ void k_embed(const float* __restrict__ x, const float* __restrict__ emb){
  int row = blockIdx.x;
  float xv = x[row];
  int idx = (int)(255.0f * xv);
  idx = min(max(idx,0),255);
  g_h[(size_t)row*EMBD + threadIdx.x] = emb[(size_t)idx*EMBD + threadIdx.x];
}

__global__ void k_rmsnorm_b(const float* __restrict__ in, const float* __restrict__ w){
  __shared__ float sh[32];
  int row = blockIdx.x;
  float v = in[(size_t)row*EMBD + threadIdx.x];
  float s = blkReduce(v*v, sh);
  float sc = rsqrtf(s/(float)EMBD + 1e-5f);
  float o = v*sc*w[threadIdx.x];
  __nv_bfloat16 h = __float2bfloat16(o);
  __nv_bfloat16 l = __float2bfloat16(o - __bfloat162float(h));
  size_t b = (size_t)row*768 + threadIdx.x;
  g_Ab[b] = h; g_Ab[b+256] = h; g_Ab[b+512] = l;
}

__global__ void k_gatednorm_b(const float* __restrict__ gw){
  __shared__ float sh[32];
  int row = blockIdx.x;
  int i0 = threadIdx.x, i1 = threadIdx.x + 256;
  float z0 = g_zx[(size_t)row*DPJ + i0], y0 = g_y[(size_t)row*DIN + i0];
  float z1 = g_zx[(size_t)row*DPJ + i1], y1 = g_y[(size_t)row*DIN + i1];
  float v0 = y0 * (z0/(1.f+__expf(-z0)));
  float v1 = y1 * (z1/(1.f+__expf(-z1)));
  float s = blkReduce(v0*v0 + v1*v1, sh);
  float sc = rsqrtf(s/(float)DIN + 1e-5f);
  float o0 = v0*sc*gw[i0];
  float o1 = v1*sc*gw[i1];
  size_t b = (size_t)row*1536;
  __nv_bfloat16 h0 = __float2bfloat16(o0);
  __nv_bfloat16 l0 = __float2bfloat16(o0 - __bfloat162float(h0));
  __nv_bfloat16 h1 = __float2bfloat16(o1);
  __nv_bfloat16 l1 = __float2bfloat16(o1 - __bfloat162float(h1));
  g_Ab[b+i0] = h0; g_Ab[b+512+i0] = h0; g_Ab[b+1024+i0] = l0;
  g_Ab[b+i1] = h1; g_Ab[b+512+i1] = h1; g_Ab[b+1024+i1] = l1;
}

// weight prep, coalesced transpose: W[K][N] fp32 -> Wb[n][3K] = [hi|lo|hi]
__global__ void __launch_bounds__(256) k_prep_w2(const float* __restrict__ W, int K, int N){
  __shared__ float t[64][65];
  int k0 = blockIdx.x*64, n0 = blockIdx.y*64;
  int tid = threadIdx.x;
  int nn = tid&63, kb = tid>>6;
  #pragma unroll
  for(int i=0;i<16;i++){
    int kk = kb + i*4;
    int n = n0+nn;
    t[kk][nn] = (n<N) ? W[(size_t)(k0+kk)*N + n] : 0.f;
  }
  __syncthreads();
  int K3 = 3*K;
  #pragma unroll
  for(int i=0;i<2;i++){
    int v = tid + i*256;
    int nl = v>>3, sg = v&7;
    union { __nv_bfloat16 h[8]; uint4 u; } H, L;
    #pragma unroll
    for(int q=0;q<8;q++){
      float w = t[sg*8+q][nl];
      __nv_bfloat16 hh = __float2bfloat16(w);
      H.h[q]=hh; L.h[q]=__float2bfloat16(w - __bfloat162float(hh));
    }
    size_t base = (size_t)(n0+nl)*K3 + k0 + sg*8;
    *(uint4*)(g_Wb + base)       = H.u;
    *(uint4*)(g_Wb + base + K)   = L.u;
    *(uint4*)(g_Wb + base + 2*K) = H.u;
  }
}

// ---------------- generalized warp-MMA bf16 GEMM (batched via blockIdx.z) ----------------
__global__ void __launch_bounds__(256,2) k_mgemm(
    const __nv_bfloat16* __restrict__ A, const __nv_bfloat16* __restrict__ Bw,
    float* __restrict__ C, const float* __restrict__ Res, int K3, int ldc, int Nreal,
    size_t strA, size_t strB, size_t strC)
{
  extern __shared__ __align__(1024) uint8_t smem[];
  A  += (size_t)blockIdx.z*strA;
  Bw += (size_t)blockIdx.z*strB;
  C  += (size_t)blockIdx.z*strC;
  if(Res) Res += (size_t)blockIdx.z*strC;
  const int tid = threadIdx.x;
  const int lane = tid & 31, wid = tid >> 5;
  const int wm = wid >> 2, wn = wid & 3;
  const int bm = blockIdx.y << 7, bn = blockIdx.x << 7;
  const uint32_t sbase = smem_u32(smem);

  uint32_t sw_off[4];
  const __nv_bfloat16 *ga[4], *gb[4];
  #pragma unroll
  for(int i=0;i<4;i++){
    int idx = tid + i*256, row = idx>>3, seg = idx&7;
    uint32_t off = (uint32_t)(row*128 + seg*16);
    sw_off[i] = off ^ ((off>>3)&0x70u);
    ga[i] = A  + (size_t)(bm+row)*K3 + seg*8;
    gb[i] = Bw + (size_t)(bn+row)*K3 + seg*8;
  }
  uint32_t arow[4], axb[4], brow[2], bxb[2];
  const uint32_t half16 = (uint32_t)(lane>>4)*16u;
  #pragma unroll
  for(int mi=0;mi<4;mi++){
    uint32_t r = (uint32_t)(wm*64 + mi*16 + (lane&15));
    arow[mi] = r*128u; axb[mi] = (arow[mi]>>3)&0x70u;
  }
  #pragma unroll
  for(int ni=0;ni<2;ni++){
    uint32_t r = (uint32_t)(wn*32 + ni*16 + (lane&15));
    brow[ni] = r*128u; bxb[ni] = (brow[ni]>>3)&0x70u;
  }
  float acc[4][4][4];
  #pragma unroll
  for(int i=0;i<4;i++)
    #pragma unroll
    for(int j=0;j<4;j++)
      #pragma unroll
      for(int q=0;q<4;q++) acc[i][j][q]=0.f;

  const int NC = K3 >> 6;
  {
    #pragma unroll
    for(int i=0;i<4;i++){
      CPA16(sbase + sw_off[i],         ga[i]);
      CPA16(sbase + 32768 + sw_off[i], gb[i]);
    }
    CPA_COMMIT();
  }
  for(int c=0;c<NC;c++){
    CPA_WAIT0();
    __syncthreads();
    if(c+1 < NC){
      uint32_t st = (uint32_t)((c+1)&1)*16384u;
      int k0 = (c+1)<<6;
      #pragma unroll
      for(int i=0;i<4;i++){
        CPA16(sbase + st + sw_off[i],         ga[i] + k0);
        CPA16(sbase + 32768 + st + sw_off[i], gb[i] + k0);
      }
      CPA_COMMIT();
    }
    const uint32_t sa = sbase + (uint32_t)(c&1)*16384u;
    const uint32_t sb = sa + 32768u;
    #pragma unroll
    for(int s=0;s<4;s++){
      const uint32_t col = (uint32_t)(s*32) + half16;
      uint32_t a[4][4], b[2][4];
      #pragma unroll
      for(int mi=0;mi<4;mi++)
        LDSM4(a[mi][0],a[mi][1],a[mi][2],a[mi][3], sa + arow[mi] + (col ^ axb[mi]));
      #pragma unroll
      for(int ni=0;ni<2;ni++)
        LDSM4(b[ni][0],b[ni][1],b[ni][2],b[ni][3], sb + brow[ni] + (col ^ bxb[ni]));
      #pragma unroll
      for(int mi=0;mi<4;mi++)
        #pragma unroll
        for(int nj=0;nj<4;nj++)
          MMA16816(acc[mi][nj], a[mi], b[nj>>1][nj&1], b[nj>>1][(nj&1)+2]);
    }
    __syncthreads();
  }
  const int mrow0 = bm + wm*64 + (lane>>2);
  const int ncol0 = bn + wn*32 + (lane&3)*2;
  #pragma unroll
  for(int mi=0;mi<4;mi++){
    int m0 = mrow0 + mi*16;
    #pragma unroll
    for(int nj=0;nj<4;nj++){
      int n0 = ncol0 + nj*8;
      float* c0 = C + (size_t)m0*ldc;
      float* c1 = C + (size_t)(m0+8)*ldc;
      if(Res){
        const float* r0 = Res + (size_t)m0*ldc;
        const float* r1 = Res + (size_t)(m0+8)*ldc;
        if(n0   < Nreal){ c0[n0]   = acc[mi][nj][0] + r0[n0];
                          c1[n0]   = acc[mi][nj][2] + r1[n0]; }
        if(n0+1 < Nreal){ c0[n0+1] = acc[mi][nj][1] + r0[n0+1];
                          c1[n0+1] = acc[mi][nj][3] + r1[n0+1]; }
      }else{
        if(n0   < Nreal){ c0[n0]   = acc[mi][nj][0];
                          c1[n0]   = acc[mi][nj][2]; }
        if(n0+1 < Nreal){ c0[n0+1] = acc[mi][nj][1];
                          c1[n0+1] = acc[mi][nj][3]; }
      }
    }
  }
}

// ---------------- tiled conv + SiLU + dt + B/C split emission ----------------
__global__ void __launch_bounds__(256) k_conv2(const float* __restrict__ cw, const float* __restrict__ cb,
                        const float* __restrict__ dtb, const float* __restrict__ alog){
  __shared__ float sx[19][256];
  int tile = blockIdx.x, cg = blockIdx.y;
  int tid = threadIdx.x;
  int rowbase = tile*16;
  int b = rowbase / LL;
  int t0 = rowbase % LL;
  int ch = cg*256 + tid;
  #pragma unroll
  for(int j=0;j<19;j++){
    int tl = t0 - 3 + j;
    sx[j][tid] = (tl>=0) ? g_zx[(size_t)(b*LL+tl)*DPJ + DIN + ch] : 0.f;
  }
  float w0=cw[ch*4], w1=cw[ch*4+1], w2=cw[ch*4+2], w3=cw[ch*4+3];
  float bias = cb[ch];
  __syncthreads();
  #pragma unroll
  for(int tt=0;tt<16;tt++){
    float acc = bias + sx[tt][tid]*w0 + sx[tt+1][tid]*w1 + sx[tt+2][tid]*w2 + sx[tt+3][tid]*w3;
    float v = acc/(1.f+__expf(-acc));
    int row = rowbase+tt;
    g_xBC[(size_t)row*CVD + ch] = v;
    if(cg==2){
      __nv_bfloat16 h = __float2bfloat16(v);
      __nv_bfloat16 l = __float2bfloat16(v - __bfloat162float(h));
      size_t o = (size_t)row*768 + tid;
      g_Bsp[o]=h; g_Bsp[o+256]=l; g_Bsp[o+512]=h;
    } else if(cg==3){
      __nv_bfloat16 h = __float2bfloat16(v);
      __nv_bfloat16 l = __float2bfloat16(v - __bfloat162float(h));
      size_t o = (size_t)row*768 + tid;
      g_Csp[o]=h; g_Csp[o+256]=h; g_Csp[o+512]=l;
    }
  }
  if(cg==0 && tid<128){
    int t = tid>>3, hh = tid&7;
    int row = rowbase + t;
    float v = g_zx[(size_t)row*DPJ + DIN + CVD + hh] + dtb[hh];
    float dtv = fmaxf(v,0.f) + log1pf(expf(-fabsf(v)));
    g_dt[row*NHD+hh] = dtv;
    g_dA[row*NHD+hh] = -expf(alog[hh])*dtv;
  }
}

__global__ void k_cumsum(){
  int bc = blockIdx.x; int h = threadIdx.x;
  if(h >= NHD) return;
  float s = 0.f;
  size_t rowb = (size_t)bc*CHKL;
  for(int l=0;l<CHKL;l++){
    s += g_dA[(rowb + l)*NHD + h];
    g_Acs[(bc*NHD+h)*CHKL + l] = s;
  }
  g_T[bc*NHD+h] = s;
}

// ---------------- transpose prep: xdT, xdecT, BT ----------------
__global__ void __launch_bounds__(256) k_trans(){
  int bc = blockIdx.x;
  __shared__ float tile[64][65];
  __shared__ float acs8[8][64];
  __shared__ float dt8[64][8];
  __shared__ float T8[8];
  __shared__ float dec[64];
  int tid = threadIdx.x;
  size_t rowb = (size_t)bc*64;
  #pragma unroll
  for(int i=0;i<2;i++){
    int idx = tid + i*256;
    acs8[idx>>6][idx&63] = g_Acs[bc*512 + idx];
    dt8[idx>>3][idx&7]   = g_dt[(rowb + (idx>>3))*8 + (idx&7)];
  }
  if(tid < 8) T8[tid] = g_T[bc*8 + tid];
  __syncthreads();

  int oc = tid>>2, lq = (tid&3)<<4;
  for(int t=0;t<12;t++){
    int colbase = (t<8) ? t*64 : 512 + (t-8)*64;
    #pragma unroll
    for(int i=0;i<16;i++){
      int idx = tid + i*256;
      tile[idx>>6][idx&63] = g_xBC[(rowb + (idx>>6))*CVD + colbase + (idx&63)];
    }
    if(t<8 && tid<64) dec[tid] = __expf(T8[t] - acs8[t][tid]);
    __syncthreads();
    if(t<8){
      union { __nv_bfloat16 h[16]; uint4 u[2]; } H, L, Hd, Ld;
      #pragma unroll
      for(int li=0;li<16;li++){
        int l = lq+li;
        float xv = tile[l][oc]*dt8[l][t];
        __nv_bfloat16 h = __float2bfloat16(xv);
        H.h[li] = h; L.h[li] = __float2bfloat16(xv - __bfloat162float(h));
        float xd = xv*dec[l];
        __nv_bfloat16 hd = __float2bfloat16(xd);
        Hd.h[li] = hd; Ld.h[li] = __float2bfloat16(xd - __bfloat162float(hd));
      }
      size_t b0 = ((size_t)bc*512 + t*64 + oc)*192;
      uint4* d0 = (uint4*)(g_xdT + b0 + lq);
      uint4* d1 = (uint4*)(g_xdT + b0 + 64 + lq);
      uint4* d2 = (uint4*)(g_xdT + b0 + 128 + lq);
      d0[0]=H.u[0]; d0[1]=H.u[1]; d1[0]=H.u[0]; d1[1]=H.u[1]; d2[0]=L.u[0]; d2[1]=L.u[1];
      uint4* e0 = (uint4*)(g_xdecT + b0 + lq);
      uint4* e1 = (uint4*)(g_xdecT + b0 + 64 + lq);
      uint4* e2 = (uint4*)(g_xdecT + b0 + 128 + lq);
      e0[0]=Hd.u[0]; e0[1]=Hd.u[1]; e1[0]=Hd.u[0]; e1[1]=Hd.u[1]; e2[0]=Ld.u[0]; e2[1]=Ld.u[1];
    }else{
      union { __nv_bfloat16 h[16]; uint4 u[2]; } H, L;
      #pragma unroll
      for(int li=0;li<16;li++){
        int l = lq+li;
        float v = tile[l][oc];
        __nv_bfloat16 h = __float2bfloat16(v);
        H.h[li] = h; L.h[li] = __float2bfloat16(v - __bfloat162float(h));
      }
      size_t b0 = ((size_t)bc*256 + (t-8)*64 + oc)*192;
      uint4* d0 = (uint4*)(g_BT + b0 + lq);
      uint4* d1 = (uint4*)(g_BT + b0 + 64 + lq);
      uint4* d2 = (uint4*)(g_BT + b0 + 128 + lq);
      d0[0]=H.u[0]; d0[1]=H.u[1]; d1[0]=L.u[0]; d1[1]=L.u[1]; d2[0]=H.u[0]; d2[1]=H.u[1];
    }
    __syncthreads();
  }
}

// ---------------- CB = C * B^T via MMA (K=768 split) ----------------
__global__ void __launch_bounds__(128) k_cb_mma(){
  int bc = blockIdx.x;
  __shared__ __align__(1024) uint8_t sA[8192];
  __shared__ __align__(1024) uint8_t sB[8192];
  int tid = threadIdx.x, lane = tid&31, wid = tid>>5;
  int wm = wid>>1, wn = wid&1;
  uint32_t aA = smem_u32(sA), aB = smem_u32(sB);
  size_t rowb = (size_t)bc*64;
  const __nv_bfloat16* A = g_Csp + rowb*768;
  const __nv_bfloat16* B = g_Bsp + rowb*768;

  float acc[2][4][4];
  #pragma unroll
  for(int i=0;i<2;i++)
    #pragma unroll
    for(int j=0;j<4;j++)
      #pragma unroll
      for(int q=0;q<4;q++) acc[i][j][q]=0.f;

  const uint32_t half16 = (uint32_t)(lane>>4)*16u;
  uint32_t arow[2], axb[2], brow[2], bxb[2];
  #pragma unroll
  for(int mi=0;mi<2;mi++){
    uint32_t r = (uint32_t)(wm*32 + mi*16 + (lane&15));
    arow[mi]=r*128u; axb[mi]=(arow[mi]>>3)&0x70u;
  }
  #pragma unroll
  for(int ni=0;ni<2;ni++){
    uint32_t r = (uint32_t)(wn*32 + ni*16 + (lane&15));
    brow[ni]=r*128u; bxb[ni]=(brow[ni]>>3)&0x70u;
  }
  for(int ch=0;ch<12;ch++){
    int k0 = ch*64;
    #pragma unroll
    for(int i=0;i<4;i++){
      int v = tid + i*128, row = v>>3, seg = v&7;
      uint32_t off = (uint32_t)(row*128 + seg*16);
      off ^= (off>>3)&0x70u;
      CPA16(aA + off, A + (size_t)row*768 + k0 + seg*8);
      CPA16(aB + off, B + (size_t)row*768 + k0 + seg*8);
    }
    CPA_COMMIT(); CPA_WAIT0();
    __syncthreads();
    #pragma unroll
    for(int s=0;s<4;s++){
      uint32_t col = (uint32_t)(s*32) + half16;
      uint32_t a[2][4], b[2][4];
      #pragma unroll
      for(int mi=0;mi<2;mi++)
        LDSM4(a[mi][0],a[mi][1],a[mi][2],a[mi][3], aA + arow[mi] + (col ^ axb[mi]));
      #pragma unroll
      for(int ni=0;ni<2;ni++)
        LDSM4(b[ni][0],b[ni][1],b[ni][2],b[ni][3], aB + brow[ni] + (col ^ bxb[ni]));
      #pragma unroll
      for(int mi=0;mi<2;mi++)
        #pragma unroll
        for(int nj=0;nj<4;nj++)
          MMA16816(acc[mi][nj], a[mi], b[nj>>1][nj&1], b[nj>>1][(nj&1)+2]);
    }
    __syncthreads();
  }
  float* CB = g_CB + (size_t)bc*4096;
  #pragma unroll
  for(int mi=0;mi<2;mi++){
    int m0 = wm*32 + mi*16 + (lane>>2);
    #pragma unroll
    for(int nj=0;nj<4;nj++){
      int n0 = wn*32 + nj*8 + (lane&3)*2;
      CB[m0*64+n0]       = acc[mi][nj][0];
      CB[m0*64+n0+1]     = acc[mi][nj][1];
      CB[(m0+8)*64+n0]   = acc[mi][nj][2];
      CB[(m0+8)*64+n0+1] = acc[mi][nj][3];
    }
  }
}

// ---------------- inter-chunk scan: fp32 run, emit split-bf16 exclusive prefix ----------------
__global__ void k_scan(){
  int bh = blockIdx.y; int b = bh>>3, h = bh&7;
  int idx = blockIdx.x*256 + threadIdx.x; // p*256+n
  int p = idx>>8, n = idx&255;
  float run = 0.f;
  for(int c=0;c<NCH;c++){
    int bc = b*NCH+c;
    size_t off = (((size_t)bc*NHD + h)*(size_t)HPD*DST) + idx;
    float s = g_state[off];
    __nv_bfloat16 hh = __float2bfloat16(run);
    __nv_bfloat16 ll = __float2bfloat16(run - __bfloat162float(hh));
    size_t ob = ((size_t)(bc*8+h)*64 + p)*768 + n;
    g_Ssp[ob] = hh; g_Ssp[ob+256] = ll; g_Ssp[ob+512] = hh;
    run = run*__expf(g_T[bc*NHD + h]) + s;
  }
}

// ---------------- Y: unified 15-chunk MMA loop ----------------
// chunks 0..11: Csp x Ssp^T (off part), scale by exp(acs_l) after chunk 11,
// chunks 12..14: L x xdT (diag part). Then + D*xh.
__global__ void __launch_bounds__(256) k_y_mma2(const float* __restrict__ Dp){
  extern __shared__ __align__(1024) uint8_t dyn[];
  // layout: Lhi 0..8K, Llo 8K..16K, A0 16K, A1 24K, B0 32K, B1 40K, acs 48K(256B)
  uint32_t sb = smem_u32(dyn);
  const uint32_t oLhi=0, oLlo=8192, oA0=16384, oA1=24576, oB0=32768, oB1=40960;
  float* acs = (float*)(dyn + 49152);
  int bc = blockIdx.x, h = blockIdx.y;
  int tid = threadIdx.x, lane = tid&31, wid = tid>>5;
  int wm = wid>>2, wn = wid&3;
  size_t rowb = (size_t)bc*64;
  int bch = bc*8+h;

  if(tid < 64) acs[tid] = g_Acs[bch*64 + tid];
  __syncthreads();
  // build L split tiles (hi at oLhi, lo at oLlo), swizzled 64x64
  #pragma unroll
  for(int i=0;i<8;i++){
    int pr = tid + i*256;         // pair index 0..2047
    int l = pr>>5, s0 = (pr&31)*2;
    float cb0 = g_CB[(size_t)bc*4096 + l*64 + s0];
    float cb1 = g_CB[(size_t)bc*4096 + l*64 + s0 + 1];
    float v0 = (s0   <= l) ? cb0*__expf(acs[l]-acs[s0])   : 0.f;
    float v1 = (s0+1 <= l) ? cb1*__expf(acs[l]-acs[s0+1]) : 0.f;
    __nv_bfloat16 h0 = __float2bfloat16(v0);
    __nv_bfloat16 l0 = __float2bfloat16(v0 - __bfloat162float(h0));
    __nv_bfloat16 h1 = __float2bfloat16(v1);
    __nv_bfloat16 l1 = __float2bfloat16(v1 - __bfloat162float(h1));
    uint32_t off = (uint32_t)(l*128 + s0*2);
    off ^= (off>>3)&0x70u;
    *(uint32_t*)(dyn + oLhi + off) = pack_bf2(h0,h1);
    *(uint32_t*)(dyn + oLlo + off) = pack_bf2(l0,l1);
  }

  const __nv_bfloat16* Ag  = g_Csp + rowb*768;
  const __nv_bfloat16* Bg0 = g_Ssp + (size_t)bch*64*768;
  const __nv_bfloat16* Bg1 = g_xdT + ((size_t)bc*512 + h*64)*192;

  const uint32_t half16 = (uint32_t)(lane>>4)*16u;
  uint32_t arow[2], axb[2];
  #pragma unroll
  for(int mi=0;mi<2;mi++){
    uint32_t r = (uint32_t)(wm*32 + mi*16 + (lane&15));
    arow[mi]=r*128u; axb[mi]=(arow[mi]>>3)&0x70u;
  }
  uint32_t brow, bxb;
  { uint32_t r = (uint32_t)(wn*16 + (lane&15)); brow=r*128u; bxb=(brow>>3)&0x70u; }

  float acc[2][2][4];
  #pragma unroll
  for(int i=0;i<2;i++)
    #pragma unroll
    for(int j=0;j<2;j++)
      #pragma unroll
      for(int q=0;q<4;q++) acc[i][j][q]=0.f;

  // staging offsets per thread
  uint32_t stoff[2];
  int strow[2], stseg[2];
  #pragma unroll
  for(int i=0;i<2;i++){
    int v = tid + i*256;
    strow[i] = v>>3; stseg[i] = v&7;
    uint32_t off = (uint32_t)(strow[i]*128 + stseg[i]*16);
    stoff[i] = off ^ ((off>>3)&0x70u);
  }
  const uint32_t oA[2] = {oA0, oA1};
  const uint32_t oB[2] = {oB0, oB1};

  // prologue: stage chunk 0
  #pragma unroll
  for(int i=0;i<2;i++){
    CPA16(sb + oA0 + stoff[i], Ag  + (size_t)strow[i]*768 + stseg[i]*8);
    CPA16(sb + oB0 + stoff[i], Bg0 + (size_t)strow[i]*768 + stseg[i]*8);
  }
  CPA_COMMIT();

  for(int j=0;j<15;j++){
    CPA_WAIT0();
    __syncthreads();
    if(j+1 < 15){
      int jn = j+1, buf = jn&1;
      if(jn < 12){
        #pragma unroll
        for(int i=0;i<2;i++){
          CPA16(sb + oA[buf] + stoff[i], Ag  + (size_t)strow[i]*768 + jn*64 + stseg[i]*8);
          CPA16(sb + oB[buf] + stoff[i], Bg0 + (size_t)strow[i]*768 + jn*64 + stseg[i]*8);
        }
      } else {
        #pragma unroll
        for(int i=0;i<2;i++)
          CPA16(sb + oB[buf] + stoff[i], Bg1 + (size_t)strow[i]*192 + (jn-12)*64 + stseg[i]*8);
      }
      CPA_COMMIT();
    }
    uint32_t aBase;
    if(j<12)       aBase = sb + oA[j&1];
    else if(j==13) aBase = sb + oLlo;
    else           aBase = sb + oLhi;
    uint32_t bBase = sb + oB[j&1];
    #pragma unroll
    for(int s=0;s<4;s++){
      uint32_t col = (uint32_t)(s*32) + half16;
      uint32_t a[2][4], b[4];
      #pragma unroll
      for(int mi=0;mi<2;mi++)
        LDSM4(a[mi][0],a[mi][1],a[mi][2],a[mi][3], aBase + arow[mi] + (col ^ axb[mi]));
      LDSM4(b[0],b[1],b[2],b[3], bBase + brow + (col ^ bxb));
      #pragma unroll
      for(int mi=0;mi<2;mi++)
        #pragma unroll
        for(int nj=0;nj<2;nj++)
          MMA16816(acc[mi][nj], a[mi], b[nj], b[nj+2]);
    }
    if(j==11){
      #pragma unroll
      for(int mi=0;mi<2;mi++){
        int r0 = wm*32 + mi*16 + (lane>>2);
        float e0 = __expf(acs[r0]), e1 = __expf(acs[r0+8]);
        #pragma unroll
        for(int nj=0;nj<2;nj++){
          acc[mi][nj][0]*=e0; acc[mi][nj][1]*=e0;
          acc[mi][nj][2]*=e1; acc[mi][nj][3]*=e1;
        }
      }
    }
  }

  float Dh = Dp[h];
  #pragma unroll
  for(int mi=0;mi<2;mi++){
    int l0 = wm*32 + mi*16 + (lane>>2);
    #pragma unroll
    for(int nj=0;nj<2;nj++){
      int p0 = wn*16 + nj*8 + (lane&3)*2;
      #pragma unroll
      for(int dl=0;dl<2;dl++){
        int l = l0 + dl*8;
        size_t xb = (rowb+l)*CVD + h*64;
        size_t yb = (rowb+l)*DIN + h*64;
        g_y[yb+p0]   = acc[mi][nj][dl*2+0] + Dh*g_xBC[xb+p0];
        g_y[yb+p0+1] = acc[mi][nj][dl*2+1] + Dh*g_xBC[xb+p0+1];
      }
    }
  }
}

// ---------------- launch ----------------
extern "C" void kernel_launch(void* const* d_in, const int* in_sizes, int n_in,
                              void* d_out, int out_size){
  const float* x    = (const float*)d_in[0];
  const float* emb  = (const float*)d_in[1];
  const float* inw  = (const float*)d_in[2];
  const float* cw   = (const float*)d_in[3];
  const float* cb   = (const float*)d_in[4];
  const float* dtb  = (const float*)d_in[5];
  const float* alog = (const float*)d_in[6];
  const float* Dp   = (const float*)d_in[7];
  const float* gw   = (const float*)d_in[8];
  const float* ow   = (const float*)d_in[9];
  const float* nw   = (const float*)d_in[10];
  const float* nfw  = (const float*)d_in[11];
  const float* hw   = (const float*)d_in[12];
  float* out = (float*)d_out;

  float *ph, *pzx, *pst;
  __nv_bfloat16 *pab, *pwb, *pxdec, *pbt;
  cudaGetSymbolAddress((void**)&ph,  g_h);
  cudaGetSymbolAddress((void**)&pzx, g_zx);
  cudaGetSymbolAddress((void**)&pst, g_state);
  cudaGetSymbolAddress((void**)&pab, g_Ab);
  cudaGetSymbolAddress((void**)&pwb, g_Wb);
  cudaGetSymbolAddress((void**)&pxdec, g_xdecT);
  cudaGetSymbolAddress((void**)&pbt, g_BT);
  cudaFuncSetAttribute(k_mgemm, cudaFuncAttributeMaxDynamicSharedMemorySize, 65536);
  cudaFuncSetAttribute(k_y_mma2, cudaFuncAttributeMaxDynamicSharedMemorySize, 49408);

  k_embed<<<ROWS,256>>>(x, emb);
  for(int i=0;i<2;i++){
    k_rmsnorm_b<<<ROWS,256>>>(ph, nw + i*EMBD);
    k_prep_w2<<<dim3(4,26),256>>>(inw + (size_t)i*EMBD*DPJ, 256, DPJ);
    k_mgemm<<<dim3(13,64,1),256,65536>>>(pab, pwb, pzx, nullptr, 768, DPJ, DPJ, 0,0,0);
    k_conv2<<<dim3(ROWS/16,4),256>>>(cw + i*CVD*4, cb + i*CVD, dtb + i*NHD, alog + i*NHD);
    k_cumsum<<<NBC,32>>>();
    k_trans<<<NBC,256>>>();
    k_cb_mma<<<NBC,128>>>();
    k_mgemm<<<dim3(2,4,NBC),256,65536>>>(pxdec, pbt, pst, nullptr, 192, 256, 256,
                                         (size_t)512*192, (size_t)256*192, (size_t)512*256);
    k_scan<<<dim3(64,32),256>>>();
    k_y_mma2<<<dim3(NBC,NHD),256,49408>>>(Dp + i*NHD);
    k_gatednorm_b<<<ROWS,256>>>(gw + i*DIN);
    k_prep_w2<<<dim3(8,4),256>>>(ow + (size_t)i*DIN*EMBD, 512, EMBD);
    k_mgemm<<<dim3(2,64,1),256,65536>>>(pab, pwb, ph, ph, 1536, EMBD, EMBD, 0,0,0);
  }
  k_rmsnorm_b<<<ROWS,256>>>(ph, nfw);
  k_prep_w2<<<dim3(4,4),256>>>(hw, 256, 256);
  k_mgemm<<<dim3(2,64,1),256,65536>>>(pab, pwb, out, nullptr, 768, 256, 256, 0,0,0);
}